// round 3
// baseline (speedup 1.0000x reference)
#include <cuda_runtime.h>
#include <cstdint>

#define T_SEQ   512
#define B_DIM   256
#define H_DIM   256
#define E_DIM   6
#define C_DIM   10
#define CLUSTER 8
#define G_COLS  16          // batch columns per cluster
#define NTHREADS 512
#define KSPLITS 8
#define KPER    32          // 256 / 8

// Dynamic smem layout (floats):
//  hbuf : [2][256][16]      = 8192   (ping-pong full-h replica, col-contiguous)
//  part : [8][128][20]      = 20480  (k-split partials, pad 20 for conflict-free STS.128)
//  wxs  : [4][32][6]        = 768
//  xes  : [6][16]           = 96
//  bsh  : [4][16]           = 64     (bias per COLUMN — faithful (H,B)+(H,) broadcast, H==B)
#define OFF_HBUF 0
#define OFF_PART 8192
#define OFF_WX   28672
#define OFF_XE   29440
#define OFF_B    29536
#define SMEM_FLOATS 29600
#define SMEM_BYTES (SMEM_FLOATS * 4)

__device__ __forceinline__ uint32_t smem_u32(const void* p) {
    return (uint32_t)__cvta_generic_to_shared(p);
}
__device__ __forceinline__ uint32_t mapa_rank(uint32_t addr, int r) {
    uint32_t ret;
    asm("mapa.shared::cluster.u32 %0, %1, %2;" : "=r"(ret) : "r"(addr), "r"(r));
    return ret;
}
__device__ __forceinline__ void st_cluster_f32(uint32_t addr, float v) {
    asm volatile("st.shared::cluster.f32 [%0], %1;" :: "r"(addr), "f"(v) : "memory");
}
__device__ __forceinline__ void cluster_sync_() {
    asm volatile("barrier.cluster.arrive.aligned;\n\tbarrier.cluster.wait.aligned;" ::: "memory");
}
// ---- packed f32x2 helpers ----
__device__ __forceinline__ uint64_t pk2(float w) {
    uint64_t r; uint32_t u = __float_as_uint(w);
    asm("mov.b64 %0, {%1, %1};" : "=l"(r) : "r"(u));
    return r;
}
__device__ __forceinline__ uint64_t fma2(uint64_t a, uint64_t b, uint64_t c) {
    uint64_t d;
    asm("fma.rn.f32x2 %0, %1, %2, %3;" : "=l"(d) : "l"(a), "l"(b), "l"(c));
    return d;
}
__device__ __forceinline__ float sigf(float x)  { return 1.0f / (1.0f + __expf(-x)); }
__device__ __forceinline__ float tanhf_(float x){ return 2.0f / (1.0f + __expf(-2.0f * x)) - 1.0f; }

extern "C" __global__ void __launch_bounds__(NTHREADS, 1) __cluster_dims__(CLUSTER, 1, 1)
lstm_cluster_kernel(const int* __restrict__ x, const float* __restrict__ emb,
                    const float* __restrict__ Wxg, const float* __restrict__ Whg, const float* __restrict__ bg,
                    const float* __restrict__ Wxi, const float* __restrict__ Whi, const float* __restrict__ bi,
                    const float* __restrict__ Wxf, const float* __restrict__ Whf, const float* __restrict__ bf,
                    const float* __restrict__ Wxo, const float* __restrict__ Who, const float* __restrict__ bo,
                    const float* __restrict__ Wp,  const float* __restrict__ bp,
                    float* __restrict__ out)
{
    extern __shared__ float sm[];
    float* hbuf = sm + OFF_HBUF;
    float* part = sm + OFF_PART;
    float* wxs  = sm + OFF_WX;
    float* xes  = sm + OFF_XE;
    float* bsh  = sm + OFF_B;

    const int tid  = threadIdx.x;
    const int rank = blockIdx.x & (CLUSTER - 1);
    const int cid  = blockIdx.x / CLUSTER;
    const int col0 = cid * G_COLS;

    // Partial-phase decomposition: 512 thr = 32 rows x 2 gate-pairs x 8 k-splits
    const int jrow = tid & 31;            // hidden row within this CTA's 32
    const int gp   = (tid >> 5) & 1;      // gate pair: {g,i} or {f,o}
    const int ks   = tid >> 6;            // k-split 0..7 (32 k each)
    const int hrow = rank * 32 + jrow;    // global hidden row

    const float* WhTab[4] = { Whg, Whi, Whf, Who };
    const float* WxTab[4] = { Wxg, Wxi, Wxf, Wxo };
    const float* bTab[4]  = { bg,  bi,  bf,  bo  };

    // ---- register-resident recurrent weights: 2 gates x 32 k = 64 fp32 ----
    float wreg[2][KPER];
    #pragma unroll
    for (int g = 0; g < 2; g++) {
        const float* wrow = WhTab[2 * gp + g] + hrow * H_DIM + ks * KPER;
        #pragma unroll
        for (int k = 0; k < KPER; k++) wreg[g][k] = wrow[k];
    }

    // ---- smem init ----
    for (int i = tid; i < H_DIM * G_COLS; i += NTHREADS) hbuf[i] = 0.0f;   // h0 = 0
    for (int i = tid; i < 4 * 32 * E_DIM; i += NTHREADS) {
        int q = i / (32 * E_DIM);
        int r = i % (32 * E_DIM);
        int j = r / E_DIM, e = r % E_DIM;
        wxs[i] = WxTab[q][(rank * 32 + j) * E_DIM + e];
    }
    if (tid < 64) {                      // bias broadcasts over trailing BATCH axis
        int q = tid >> 4, c = tid & 15;
        bsh[tid] = bTab[q][col0 + c];
    }
    __syncthreads();

    uint32_t mybase = smem_u32(hbuf);
    uint32_t peer[CLUSTER];
    #pragma unroll
    for (int r = 0; r < CLUSTER; r++) peer[r] = mapa_rank(mybase, r);

    cluster_sync_();

    // Finalize mapping: thread -> (row fj, column fcol) : one h value each
    const int fj   = tid >> 4;           // 0..31
    const int fcol = tid & 15;           // 0..15
    float cst = 0.0f;                    // cell state, register-resident

    int p = 0;
    for (int t = 0; t < T_SEQ; t++) {
        if (tid < G_COLS) {
            int xi = x[(col0 + tid) * T_SEQ + t];
            const float* er = emb + xi * E_DIM;
            #pragma unroll
            for (int e = 0; e < E_DIM; e++) xes[e * G_COLS + tid] = er[e];
        }

        // ---- partial mat-vec: 32 k-iters, 2 gates, 16 cols as 8 f32x2 ----
        uint64_t acc[2][8];
        #pragma unroll
        for (int g = 0; g < 2; g++)
            #pragma unroll
            for (int c = 0; c < 8; c++) acc[g][c] = 0ull;

        const ulonglong2* hb2 =
            (const ulonglong2*)(hbuf + p * (H_DIM * G_COLS)) + (size_t)ks * KPER * 4;
        #pragma unroll
        for (int k = 0; k < KPER; k++) {
            const ulonglong2 v0 = hb2[k * 4 + 0];
            const ulonglong2 v1 = hb2[k * 4 + 1];
            const ulonglong2 v2 = hb2[k * 4 + 2];
            const ulonglong2 v3 = hb2[k * 4 + 3];
            #pragma unroll
            for (int g = 0; g < 2; g++) {
                const uint64_t wp = pk2(wreg[g][k]);
                acc[g][0] = fma2(wp, v0.x, acc[g][0]);
                acc[g][1] = fma2(wp, v0.y, acc[g][1]);
                acc[g][2] = fma2(wp, v1.x, acc[g][2]);
                acc[g][3] = fma2(wp, v1.y, acc[g][3]);
                acc[g][4] = fma2(wp, v2.x, acc[g][4]);
                acc[g][5] = fma2(wp, v2.y, acc[g][5]);
                acc[g][6] = fma2(wp, v3.x, acc[g][6]);
                acc[g][7] = fma2(wp, v3.y, acc[g][7]);
            }
        }
        // store partials: part[ks][gate*32+jrow][col], stride 20 -> conflict-free
        #pragma unroll
        for (int g = 0; g < 2; g++) {
            float* pr = part + (ks * 128 + (2 * gp + g) * 32 + jrow) * 20;
            ((ulonglong2*)pr)[0] = make_ulonglong2(acc[g][0], acc[g][1]);
            ((ulonglong2*)pr)[1] = make_ulonglong2(acc[g][2], acc[g][3]);
            ((ulonglong2*)pr)[2] = make_ulonglong2(acc[g][4], acc[g][5]);
            ((ulonglong2*)pr)[3] = make_ulonglong2(acc[g][6], acc[g][7]);
        }
        __syncthreads();

        // ---- finalize: sum 8 k-splits + Wx*x + bias, gates, c/h update ----
        float xe[E_DIM];
        #pragma unroll
        for (int e = 0; e < E_DIM; e++) xe[e] = xes[e * 16 + fcol];

        float pre[4];
        #pragma unroll
        for (int q = 0; q < 4; q++) {
            const int rl = q * 32 + fj;
            float s = bsh[q * 16 + fcol];
            #pragma unroll
            for (int kss = 0; kss < KSPLITS; kss++)
                s += part[(kss * 128 + rl) * 20 + fcol];
            #pragma unroll
            for (int e = 0; e < E_DIM; e++)
                s = fmaf(wxs[rl * E_DIM + e], xe[e], s);
            pre[q] = s;
        }

        float g  = tanhf_(pre[0]);
        float ig = sigf(pre[1]);
        float fg = sigf(pre[2]);
        float og = sigf(pre[3]);
        cst = fmaf(g, ig, cst * fg);
        const float hn = tanhf_(cst) * og;

        // ---- broadcast h value to all 8 CTAs' hbuf[p^1] ----
        const uint32_t off = (uint32_t)((((p ^ 1) * (H_DIM * G_COLS)) +
                                        (rank * 32 + fj) * G_COLS + fcol) * 4);
        #pragma unroll
        for (int r = 0; r < CLUSTER; r++)
            st_cluster_f32(peer[r] + off, hn);

        cluster_sync_();
        p ^= 1;
    }

    // ---- projection: out[b, c] = sum_k Wp[c,k] h[k,b] + bp[c] ----
    if (rank == 0 && tid < G_COLS * C_DIM) {
        const int col = tid / C_DIM;
        const int cls = tid % C_DIM;
        const float* wpr = Wp + cls * H_DIM;
        const float* hfin = hbuf + p * (H_DIM * G_COLS);
        float s = bp[cls];
        #pragma unroll 8
        for (int k = 0; k < H_DIM; k++)
            s = fmaf(wpr[k], hfin[k * G_COLS + col], s);
        out[(col0 + col) * C_DIM + cls] = s;
    }
}

extern "C" void kernel_launch(void* const* d_in, const int* in_sizes, int n_in,
                              void* d_out, int out_size) {
    (void)in_sizes; (void)n_in; (void)out_size;
    const int*   x   = (const int*)  d_in[0];
    const float* emb = (const float*)d_in[1];
    const float* Wxg = (const float*)d_in[2];
    const float* Whg = (const float*)d_in[3];
    const float* bg  = (const float*)d_in[4];
    const float* Wxi = (const float*)d_in[5];
    const float* Whi = (const float*)d_in[6];
    const float* bi  = (const float*)d_in[7];
    const float* Wxf = (const float*)d_in[8];
    const float* Whf = (const float*)d_in[9];
    const float* bf  = (const float*)d_in[10];
    const float* Wxo = (const float*)d_in[11];
    const float* Who = (const float*)d_in[12];
    const float* bo  = (const float*)d_in[13];
    const float* Wp  = (const float*)d_in[14];
    const float* bp  = (const float*)d_in[15];
    float* out = (float*)d_out;

    cudaFuncSetAttribute(lstm_cluster_kernel,
                         cudaFuncAttributeMaxDynamicSharedMemorySize, SMEM_BYTES);
    lstm_cluster_kernel<<<(B_DIM / G_COLS) * CLUSTER, NTHREADS, SMEM_BYTES>>>(
        x, emb, Wxg, Whg, bg, Wxi, Whi, bi, Wxf, Whf, bf, Wxo, Who, bo, Wp, bp, out);
}

// round 4
// speedup vs baseline: 1.0734x; 1.0734x over previous
#include <cuda_runtime.h>
#include <cstdint>

#define T_SEQ   512
#define B_DIM   256
#define H_DIM   256
#define E_DIM   6
#define C_DIM   10
#define CLUSTER 8
#define G_COLS  16          // batch columns per cluster
#define NTHREADS 256

// Dynamic smem layout (floats):
//  hbuf : [2][256][16]      = 8192   (ping-pong full-h replica, col-contiguous)
//  part : [4][128][20]      = 10240  (k-split partials, pad 20 for conflict-free STS.128)
//  wxs  : [4][32][6]        = 768
//  xes  : [6][16]           = 96
//  bsh  : [4][16]           = 64     (bias per COLUMN — faithful (H,B)+(H,) broadcast, H==B)
#define OFF_HBUF 0
#define OFF_PART 8192
#define OFF_WX   18432
#define OFF_XE   19200
#define OFF_B    19296
#define SMEM_FLOATS 19360
#define SMEM_BYTES (SMEM_FLOATS * 4)

__device__ __forceinline__ uint32_t smem_u32(const void* p) {
    return (uint32_t)__cvta_generic_to_shared(p);
}
__device__ __forceinline__ uint32_t mapa_rank(uint32_t addr, int r) {
    uint32_t ret;
    asm("mapa.shared::cluster.u32 %0, %1, %2;" : "=r"(ret) : "r"(addr), "r"(r));
    return ret;
}
__device__ __forceinline__ void st_cluster_u64(uint32_t addr, uint64_t v) {
    asm volatile("st.shared::cluster.u64 [%0], %1;" :: "r"(addr), "l"(v) : "memory");
}
__device__ __forceinline__ void cluster_sync_() {
    asm volatile("barrier.cluster.arrive.aligned;\n\tbarrier.cluster.wait.aligned;" ::: "memory");
}
// ---- packed f32x2 helpers ----
__device__ __forceinline__ uint64_t pk2(float w) {
    uint64_t r; uint32_t u = __float_as_uint(w);
    asm("mov.b64 %0, {%1, %1};" : "=l"(r) : "r"(u));
    return r;
}
__device__ __forceinline__ uint64_t pk2ab(float a, float b) {
    uint64_t r; uint32_t ua = __float_as_uint(a), ub = __float_as_uint(b);
    asm("mov.b64 %0, {%1, %2};" : "=l"(r) : "r"(ua), "r"(ub));
    return r;
}
__device__ __forceinline__ float2 unpk2(uint64_t v) {
    uint32_t lo, hi;
    asm("mov.b64 {%0, %1}, %2;" : "=r"(lo), "=r"(hi) : "l"(v));
    return make_float2(__uint_as_float(lo), __uint_as_float(hi));
}
__device__ __forceinline__ uint64_t fma2(uint64_t a, uint64_t b, uint64_t c) {
    uint64_t d;
    asm("fma.rn.f32x2 %0, %1, %2, %3;" : "=l"(d) : "l"(a), "l"(b), "l"(c));
    return d;
}
__device__ __forceinline__ uint64_t add2(uint64_t a, uint64_t b) {
    uint64_t d;
    asm("add.rn.f32x2 %0, %1, %2;" : "=l"(d) : "l"(a), "l"(b));
    return d;
}

// ================= MUFU-free activations (fma/alu pipes only) =================
// 2^y for |y| <= ~25, via rint-magic + deg-6 Taylor of 2^f + exponent assembly.
__device__ __forceinline__ float exp2m(float y) {
    float fk = y + 12582912.0f;                     // round-to-nearest int (magic)
    int   n  = __float_as_int(fk) - 0x4B400000;     // integer part
    float f  = y - (fk - 12582912.0f);              // frac in [-0.5, 0.5]
    float p  = 1.54035e-4f;
    p = fmaf(p, f, 1.3333558e-3f);
    p = fmaf(p, f, 9.6181291e-3f);
    p = fmaf(p, f, 5.5504109e-2f);
    p = fmaf(p, f, 2.4022651e-1f);
    p = fmaf(p, f, 6.9314718e-1f);
    p = fmaf(p, f, 1.0f);
    return p * __int_as_float((n + 127) << 23);     // * 2^n
}
// 1/d for d in [1, ~2^22): bit-trick seed + 3 Newton iterations (err ~1e-7)
__device__ __forceinline__ float rcp_fma(float d) {
    float y = __int_as_float(0x7EF311C3 - __float_as_int(d));
    float e;
    e = fmaf(-d, y, 1.0f); y = fmaf(y, e, y);
    e = fmaf(-d, y, 1.0f); y = fmaf(y, e, y);
    e = fmaf(-d, y, 1.0f); y = fmaf(y, e, y);
    return y;
}
__device__ __forceinline__ float sig_fma(float x) {
    x = fminf(fmaxf(x, -14.0f), 14.0f);             // sigma(14)=1-8e-7: clamp err negligible
    float u = exp2m(-1.4426950408f * x);
    return rcp_fma(1.0f + u);
}
__device__ __forceinline__ float tanh_fma(float x) {
    x = fminf(fmaxf(x, -7.0f), 7.0f);               // tanh(7)=1-1.8e-6
    float u = exp2m(-2.8853900817f * x);
    return fmaf(2.0f, rcp_fma(1.0f + u), -1.0f);
}
// ==============================================================================

extern "C" __global__ void __launch_bounds__(NTHREADS, 1) __cluster_dims__(CLUSTER, 1, 1)
lstm_cluster_kernel(const int* __restrict__ x, const float* __restrict__ emb,
                    const float* __restrict__ Wxg, const float* __restrict__ Whg, const float* __restrict__ bg,
                    const float* __restrict__ Wxi, const float* __restrict__ Whi, const float* __restrict__ bi,
                    const float* __restrict__ Wxf, const float* __restrict__ Whf, const float* __restrict__ bf,
                    const float* __restrict__ Wxo, const float* __restrict__ Who, const float* __restrict__ bo,
                    const float* __restrict__ Wp,  const float* __restrict__ bp,
                    float* __restrict__ out)
{
    extern __shared__ float sm[];
    float* hbuf = sm + OFF_HBUF;
    float* part = sm + OFF_PART;
    float* wxs  = sm + OFF_WX;
    float* xes  = sm + OFF_XE;
    float* bsh  = sm + OFF_B;

    const int tid  = threadIdx.x;
    const int rank = blockIdx.x & (CLUSTER - 1);
    const int cid  = blockIdx.x / CLUSTER;
    const int col0 = cid * G_COLS;

    // Partial-phase decomposition: 256 thr = 32 rows x 2 gate-pairs x 4 k-splits
    const int jrow = tid & 31;            // hidden row within this CTA's 32
    const int gp   = (tid >> 5) & 1;      // gate pair: {g,i} or {f,o}
    const int ks   = tid >> 6;            // k-split 0..3 (64 k each)
    const int hrow = rank * 32 + jrow;    // global hidden row

    const float* WhTab[4] = { Whg, Whi, Whf, Who };
    const float* WxTab[4] = { Wxg, Wxi, Wxf, Wxo };
    const float* bTab[4]  = { bg,  bi,  bf,  bo  };

    // ---- register-resident recurrent weights: 2 gates x 64 k = 128 fp32 ----
    float wreg[2][64];
    #pragma unroll
    for (int g = 0; g < 2; g++) {
        const float* wrow = WhTab[2 * gp + g] + hrow * H_DIM + ks * 64;
        #pragma unroll
        for (int k = 0; k < 64; k++) wreg[g][k] = wrow[k];
    }

    // ---- smem init ----
    for (int i = tid; i < H_DIM * G_COLS; i += NTHREADS) hbuf[i] = 0.0f;   // h0 = 0
    for (int i = tid; i < 4 * 32 * E_DIM; i += NTHREADS) {
        int q = i / (32 * E_DIM);
        int r = i % (32 * E_DIM);
        int j = r / E_DIM, e = r % E_DIM;
        wxs[i] = WxTab[q][(rank * 32 + j) * E_DIM + e];
    }
    if (tid < 64) {                      // bias broadcasts over trailing BATCH axis
        int q = tid >> 4, c = tid & 15;
        bsh[tid] = bTab[q][col0 + c];
    }
    __syncthreads();

    uint32_t mybase = smem_u32(hbuf);
    uint32_t peer[CLUSTER];
    #pragma unroll
    for (int r = 0; r < CLUSTER; r++) peer[r] = mapa_rank(mybase, r);

    cluster_sync_();

    // Finalize mapping: thread -> (row fj, column pair 2*fcp, 2*fcp+1)
    const int fj  = tid >> 3;            // 0..31
    const int fcp = tid & 7;             // 0..7
    float cstA = 0.0f, cstB = 0.0f;      // cell states for the two columns

    int p = 0;
    for (int t = 0; t < T_SEQ; t++) {
        if (tid < G_COLS) {
            int xi = x[(col0 + tid) * T_SEQ + t];
            const float* er = emb + xi * E_DIM;
            #pragma unroll
            for (int e = 0; e < E_DIM; e++) xes[e * G_COLS + tid] = er[e];
        }

        // ---- partial mat-vec: 64 k-iters, 2 gates, 16 cols as 8 f32x2 ----
        uint64_t acc[2][8];
        #pragma unroll
        for (int g = 0; g < 2; g++)
            #pragma unroll
            for (int c = 0; c < 8; c++) acc[g][c] = 0ull;

        const ulonglong2* hb2 =
            (const ulonglong2*)(hbuf + p * (H_DIM * G_COLS)) + (size_t)ks * 64 * 4;
        #pragma unroll
        for (int k = 0; k < 64; k++) {
            const ulonglong2 v0 = hb2[k * 4 + 0];
            const ulonglong2 v1 = hb2[k * 4 + 1];
            const ulonglong2 v2 = hb2[k * 4 + 2];
            const ulonglong2 v3 = hb2[k * 4 + 3];
            #pragma unroll
            for (int g = 0; g < 2; g++) {
                const uint64_t wp = pk2(wreg[g][k]);
                acc[g][0] = fma2(wp, v0.x, acc[g][0]);
                acc[g][1] = fma2(wp, v0.y, acc[g][1]);
                acc[g][2] = fma2(wp, v1.x, acc[g][2]);
                acc[g][3] = fma2(wp, v1.y, acc[g][3]);
                acc[g][4] = fma2(wp, v2.x, acc[g][4]);
                acc[g][5] = fma2(wp, v2.y, acc[g][5]);
                acc[g][6] = fma2(wp, v3.x, acc[g][6]);
                acc[g][7] = fma2(wp, v3.y, acc[g][7]);
            }
        }
        // store partials: part[ks][gate*32+jrow][col], stride 20 -> conflict-free
        #pragma unroll
        for (int g = 0; g < 2; g++) {
            float* pr = part + (ks * 128 + (2 * gp + g) * 32 + jrow) * 20;
            ((ulonglong2*)pr)[0] = make_ulonglong2(acc[g][0], acc[g][1]);
            ((ulonglong2*)pr)[1] = make_ulonglong2(acc[g][2], acc[g][3]);
            ((ulonglong2*)pr)[2] = make_ulonglong2(acc[g][4], acc[g][5]);
            ((ulonglong2*)pr)[3] = make_ulonglong2(acc[g][6], acc[g][7]);
        }
        __syncthreads();

        // ---- finalize: sum 4 k-splits + Wx*x + bias, gates, c/h update ----
        uint64_t xe2[E_DIM];
        #pragma unroll
        for (int e = 0; e < E_DIM; e++)
            xe2[e] = *(const uint64_t*)&xes[e * 16 + 2 * fcp];

        float preA[4], preB[4];
        #pragma unroll
        for (int q = 0; q < 4; q++) {
            const int rl = q * 32 + fj;
            uint64_t s2 = *(const uint64_t*)&bsh[q * 16 + 2 * fcp];
            #pragma unroll
            for (int kss = 0; kss < 4; kss++)
                s2 = add2(s2, *(const uint64_t*)&part[(kss * 128 + rl) * 20 + 2 * fcp]);
            #pragma unroll
            for (int e = 0; e < E_DIM; e++)
                s2 = fma2(pk2(wxs[rl * E_DIM + e]), xe2[e], s2);
            float2 sv = unpk2(s2);
            preA[q] = sv.x; preB[q] = sv.y;
        }

        float gA = tanh_fma(preA[0]), iA = sig_fma(preA[1]), fA = sig_fma(preA[2]), oA = sig_fma(preA[3]);
        float gB = tanh_fma(preB[0]), iB = sig_fma(preB[1]), fB = sig_fma(preB[2]), oB = sig_fma(preB[3]);
        cstA = fmaf(gA, iA, cstA * fA);
        cstB = fmaf(gB, iB, cstB * fB);
        const float hnA = tanh_fma(cstA) * oA;
        const float hnB = tanh_fma(cstB) * oB;
        const uint64_t hn2 = pk2ab(hnA, hnB);

        // ---- broadcast h column-pair to all 8 CTAs' hbuf[p^1] ----
        const uint32_t off = (uint32_t)((((p ^ 1) * (H_DIM * G_COLS)) +
                                        (rank * 32 + fj) * G_COLS + 2 * fcp) * 4);
        #pragma unroll
        for (int r = 0; r < CLUSTER; r++)
            st_cluster_u64(peer[r] + off, hn2);

        cluster_sync_();
        p ^= 1;
    }

    // ---- projection: out[b, c] = sum_k Wp[c,k] h[k,b] + bp[c] ----
    if (rank == 0 && tid < G_COLS * C_DIM) {
        const int col = tid / C_DIM;
        const int cls = tid % C_DIM;
        const float* wpr = Wp + cls * H_DIM;
        const float* hfin = hbuf + p * (H_DIM * G_COLS);
        float s = bp[cls];
        #pragma unroll 8
        for (int k = 0; k < H_DIM; k++)
            s = fmaf(wpr[k], hfin[k * G_COLS + col], s);
        out[(col0 + col) * C_DIM + cls] = s;
    }
}

extern "C" void kernel_launch(void* const* d_in, const int* in_sizes, int n_in,
                              void* d_out, int out_size) {
    (void)in_sizes; (void)n_in; (void)out_size;
    const int*   x   = (const int*)  d_in[0];
    const float* emb = (const float*)d_in[1];
    const float* Wxg = (const float*)d_in[2];
    const float* Whg = (const float*)d_in[3];
    const float* bg  = (const float*)d_in[4];
    const float* Wxi = (const float*)d_in[5];
    const float* Whi = (const float*)d_in[6];
    const float* bi  = (const float*)d_in[7];
    const float* Wxf = (const float*)d_in[8];
    const float* Whf = (const float*)d_in[9];
    const float* bf  = (const float*)d_in[10];
    const float* Wxo = (const float*)d_in[11];
    const float* Who = (const float*)d_in[12];
    const float* bo  = (const float*)d_in[13];
    const float* Wp  = (const float*)d_in[14];
    const float* bp  = (const float*)d_in[15];
    float* out = (float*)d_out;

    cudaFuncSetAttribute(lstm_cluster_kernel,
                         cudaFuncAttributeMaxDynamicSharedMemorySize, SMEM_BYTES);
    lstm_cluster_kernel<<<(B_DIM / G_COLS) * CLUSTER, NTHREADS, SMEM_BYTES>>>(
        x, emb, Wxg, Whg, bg, Wxi, Whi, bi, Wxf, Whf, bf, Wxo, Who, bo, Wp, bp, out);
}

// round 6
// speedup vs baseline: 1.4715x; 1.3709x over previous
#include <cuda_runtime.h>
#include <cuda_bf16.h>
#include <cstdint>

#define T_SEQ   512
#define B_DIM   256
#define H_DIM   256
#define E_DIM   6
#define C_DIM   10
#define CLUSTER 8
#define G_COLS  16
#define NTHREADS 256
#define KC_N    17                  // 17 k-chunks of 16 -> K = 272
#define KB      280                 // bf16 elems per column (padded k-stride)

#define B_MAT   (G_COLS * KB * 2)   // 8960 bytes per B matrix
#define OFF_B    0                  // 4 matrices: [p][hi/lo]
#define OFF_PART (4 * B_MAT)        // 35840 : 128 x 20 fp32
#define SMEM_BYTES (OFF_PART + 128 * 20 * 4)   // 46080

__device__ __forceinline__ uint32_t smem_u32(const void* p) {
    return (uint32_t)__cvta_generic_to_shared(p);
}
__device__ __forceinline__ uint32_t mapa_rank(uint32_t addr, int r) {
    uint32_t ret;
    asm("mapa.shared::cluster.u32 %0, %1, %2;" : "=r"(ret) : "r"(addr), "r"(r));
    return ret;
}
__device__ __forceinline__ void st_cluster_u32(uint32_t addr, uint32_t v) {
    asm volatile("st.shared::cluster.u32 [%0], %1;" :: "r"(addr), "r"(v) : "memory");
}
__device__ __forceinline__ void cluster_sync_() {
    asm volatile("barrier.cluster.arrive.aligned;\n\tbarrier.cluster.wait.aligned;" ::: "memory");
}
// m16n8k16 row.col bf16 -> f32, acc in place
__device__ __forceinline__ void mma16816(float c[4], const uint32_t a[4],
                                         uint32_t b0, uint32_t b1) {
    asm volatile("mma.sync.aligned.m16n8k16.row.col.f32.bf16.bf16.f32 "
                 "{%0,%1,%2,%3}, {%4,%5,%6,%7}, {%8,%9}, {%0,%1,%2,%3};"
                 : "+f"(c[0]), "+f"(c[1]), "+f"(c[2]), "+f"(c[3])
                 : "r"(a[0]), "r"(a[1]), "r"(a[2]), "r"(a[3]), "r"(b0), "r"(b1));
}
__device__ __forceinline__ uint32_t pack_hi(float a, float b) {
    __nv_bfloat162 t = __floats2bfloat162_rn(a, b);
    return *(uint32_t*)&t;
}
__device__ __forceinline__ void split2(float a, float b, uint32_t& hp, uint32_t& lp) {
    float ah = __bfloat162float(__float2bfloat16(a));
    float bh = __bfloat162float(__float2bfloat16(b));
    hp = pack_hi(ah, bh);
    lp = pack_hi(a - ah, b - bh);
}
__device__ __forceinline__ float sigf(float x)  { return __fdividef(1.0f, 1.0f + __expf(-x)); }
__device__ __forceinline__ float tanhf_(float x){ return __fdividef(2.0f, 1.0f + __expf(-2.0f * x)) - 1.0f; }

extern "C" __global__ void __launch_bounds__(NTHREADS, 1) __cluster_dims__(CLUSTER, 1, 1)
lstm_hmma_kernel(const int* __restrict__ x, const float* __restrict__ emb,
                 const float* __restrict__ Wxg, const float* __restrict__ Whg, const float* __restrict__ bg,
                 const float* __restrict__ Wxi, const float* __restrict__ Whi, const float* __restrict__ bi,
                 const float* __restrict__ Wxf, const float* __restrict__ Whf, const float* __restrict__ bf,
                 const float* __restrict__ Wxo, const float* __restrict__ Who, const float* __restrict__ bo,
                 const float* __restrict__ Wp,  const float* __restrict__ bp,
                 float* __restrict__ out)
{
    extern __shared__ char sb[];
    float* part = (float*)(sb + OFF_PART);
    const uint32_t sb32 = smem_u32(sb);

    const int tid  = threadIdx.x;
    const int wid  = tid >> 5;
    const int lane = tid & 31;
    const int g    = lane >> 2;       // groupID 0..7
    const int tg   = lane & 3;        // thread-in-group
    const int rank = blockIdx.x & (CLUSTER - 1);
    const int cid  = blockIdx.x / CLUSTER;
    const int col0 = cid * G_COLS;

    const float* WhTab[4] = { Whg, Whi, Whf, Who };
    const float* WxTab[4] = { Wxg, Wxi, Wxf, Wxo };
    const float* bTab[4]  = { bg,  bi,  bf,  bo  };

    // ---- A fragments, register-resident (hi/lo bf16 split) ----
    // warp w owns A rows 16w..16w+15 (gate-row r: gate = r>>5, j = r&31)
    uint32_t aHi[KC_N][4], aLo[KC_N][4];
    {
        const int ra = 16 * wid + g;       // rows for a0/a2
        const int rb = ra + 8;             // rows for a1/a3
        auto getA = [&](int r, int k) -> float {
            int gate = r >> 5, j = r & 31;
            int row = rank * 32 + j;
            if (k < 256) return WhTab[gate][row * H_DIM + k];
            if (k < 260) return (k - 256 == gate) ? 1.0f : 0.0f;   // bias indicator
            if (k < 266) return WxTab[gate][row * E_DIM + (k - 260)];
            return 0.0f;
        };
        #pragma unroll
        for (int kc = 0; kc < KC_N; kc++) {
            const int k0 = kc * 16 + 2 * tg;
            split2(getA(ra, k0),     getA(ra, k0 + 1), aHi[kc][0], aLo[kc][0]);
            split2(getA(rb, k0),     getA(rb, k0 + 1), aHi[kc][1], aLo[kc][1]);
            split2(getA(ra, k0 + 8), getA(ra, k0 + 9), aHi[kc][2], aLo[kc][2]);
            split2(getA(rb, k0 + 8), getA(rb, k0 + 9), aHi[kc][3], aLo[kc][3]);
        }
    }

    // ---- zero all 4 B matrices (h0 = 0, pad = 0) ----
    for (int i = tid; i < (4 * B_MAT) / 4; i += NTHREADS)
        ((uint32_t*)(sb + OFF_B))[i] = 0u;
    __syncthreads();

    // ---- bias rows (k=256..259) into both p-buffers; emb(t=0) into buffer 0 ----
    if (tid < G_COLS) {
        const int col = tid;
        #pragma unroll
        for (int q = 0; q < 4; q++) {
            float v  = bTab[q][col0 + col];
            float vh = __bfloat162float(__float2bfloat16(v));
            __nv_bfloat16 hb = __float2bfloat16(vh);
            __nv_bfloat16 lb = __float2bfloat16(v - vh);
            #pragma unroll
            for (int pb = 0; pb < 2; pb++) {
                char* Bh = sb + OFF_B + (pb * 2 + 0) * B_MAT;
                char* Bl = Bh + B_MAT;
                *(__nv_bfloat16*)(Bh + col * (KB * 2) + (256 + q) * 2) = hb;
                *(__nv_bfloat16*)(Bl + col * (KB * 2) + (256 + q) * 2) = lb;
            }
        }
        int xi = x[(col0 + col) * T_SEQ + 0];
        const float* er = emb + xi * E_DIM;
        char* Bh = sb + OFF_B;            // buffer p=0, hi
        char* Bl = Bh + B_MAT;
        #pragma unroll
        for (int e = 0; e < E_DIM; e += 2) {
            uint32_t hp, lp;
            split2(er[e], er[e + 1], hp, lp);
            *(uint32_t*)(Bh + col * (KB * 2) + (260 + e) * 2) = hp;
            *(uint32_t*)(Bl + col * (KB * 2) + (260 + e) * 2) = lp;
        }
    }

    uint32_t peer[CLUSTER];
    #pragma unroll
    for (int r = 0; r < CLUSTER; r++) peer[r] = mapa_rank(sb32, r);

    __syncthreads();
    cluster_sync_();     // peers must not write into our B before init done

    // finalize mapping: thread -> rows (2fj, 2fj+1), column fcl
    const int fj  = tid >> 4;        // 0..15
    const int fcl = tid & 15;        // 0..15
    float cst0 = 0.0f, cst1 = 0.0f;

    const int coff0 = (0 + g) * (KB * 2);   // byte col offsets for the 2 n-tiles
    const int coff1 = (8 + g) * (KB * 2);

    int p = 0;
    for (int t = 0; t < T_SEQ; t++) {
        const char* Bh = sb + OFF_B + (p * 2 + 0) * B_MAT;
        const char* Bl = Bh + B_MAT;

        float acc0[4] = {0.f, 0.f, 0.f, 0.f};
        float acc1[4] = {0.f, 0.f, 0.f, 0.f};

        #pragma unroll
        for (int kc = 0; kc < KC_N; kc++) {
            const int kb = (kc * 16 + 2 * tg) * 2;   // byte offset of b0's k
            // n-tile 0
            uint32_t bh0 = *(const uint32_t*)(Bh + coff0 + kb);
            uint32_t bh1 = *(const uint32_t*)(Bh + coff0 + kb + 16);
            uint32_t bl0 = *(const uint32_t*)(Bl + coff0 + kb);
            uint32_t bl1 = *(const uint32_t*)(Bl + coff0 + kb + 16);
            mma16816(acc0, aHi[kc], bh0, bh1);
            mma16816(acc0, aLo[kc], bh0, bh1);
            mma16816(acc0, aHi[kc], bl0, bl1);
            // n-tile 1
            uint32_t ch0 = *(const uint32_t*)(Bh + coff1 + kb);
            uint32_t ch1 = *(const uint32_t*)(Bh + coff1 + kb + 16);
            uint32_t cl0 = *(const uint32_t*)(Bl + coff1 + kb);
            uint32_t cl1 = *(const uint32_t*)(Bl + coff1 + kb + 16);
            mma16816(acc1, aHi[kc], ch0, ch1);
            mma16816(acc1, aLo[kc], ch0, ch1);
            mma16816(acc1, aHi[kc], cl0, cl1);
        }

        // ---- store D tiles to part[row][col] (row = gate*32 + j), stride 20 ----
        {
            float* pr0 = part + (16 * wid + g) * 20;
            float* pr1 = pr0 + 8 * 20;
            *(float2*)(pr0 + 2 * tg)     = make_float2(acc0[0], acc0[1]);
            *(float2*)(pr1 + 2 * tg)     = make_float2(acc0[2], acc0[3]);
            *(float2*)(pr0 + 8 + 2 * tg) = make_float2(acc1[0], acc1[1]);
            *(float2*)(pr1 + 8 + 2 * tg) = make_float2(acc1[2], acc1[3]);
        }
        __syncthreads();

        // ---- prefetch next-step embedding rows into local B[p^1] ----
        if (tid < G_COLS && t + 1 < T_SEQ) {
            const int col = tid;
            int xi = x[(col0 + col) * T_SEQ + (t + 1)];
            const float* er = emb + xi * E_DIM;
            char* Nh = sb + OFF_B + ((p ^ 1) * 2 + 0) * B_MAT;
            char* Nl = Nh + B_MAT;
            #pragma unroll
            for (int e = 0; e < E_DIM; e += 2) {
                uint32_t hp, lp;
                split2(er[e], er[e + 1], hp, lp);
                *(uint32_t*)(Nh + col * (KB * 2) + (260 + e) * 2) = hp;
                *(uint32_t*)(Nl + col * (KB * 2) + (260 + e) * 2) = lp;
            }
        }

        // ---- finalize: gates + c/h update for rows 2fj, 2fj+1, col fcl ----
        float pre0[4], pre1[4];
        #pragma unroll
        for (int q = 0; q < 4; q++) {
            pre0[q] = part[(q * 32 + 2 * fj)     * 20 + fcl];
            pre1[q] = part[(q * 32 + 2 * fj + 1) * 20 + fcl];
        }
        float g0 = tanhf_(pre0[0]), i0 = sigf(pre0[1]), f0 = sigf(pre0[2]), o0 = sigf(pre0[3]);
        float g1 = tanhf_(pre1[0]), i1 = sigf(pre1[1]), f1 = sigf(pre1[2]), o1 = sigf(pre1[3]);
        cst0 = fmaf(g0, i0, cst0 * f0);
        cst1 = fmaf(g1, i1, cst1 * f1);
        const float hn0 = tanhf_(cst0) * o0;
        const float hn1 = tanhf_(cst1) * o1;

        uint32_t hp, lp;
        split2(hn0, hn1, hp, lp);     // two consecutive k-rows, same column

        // ---- broadcast h (k = rank*32 + 2fj, +1) to all peers' B[p^1] ----
        const uint32_t ohi = (uint32_t)(OFF_B + ((p ^ 1) * 2 + 0) * B_MAT +
                                        fcl * (KB * 2) + (rank * 32 + 2 * fj) * 2);
        #pragma unroll
        for (int r = 0; r < CLUSTER; r++) {
            st_cluster_u32(peer[r] + ohi, hp);
            st_cluster_u32(peer[r] + ohi + B_MAT, lp);
        }
        cluster_sync_();
        p ^= 1;
    }

    // ---- projection: out[b, c] = sum_k Wp[c,k] h[k,b] + bp[c] ----
    if (rank == 0 && tid < G_COLS * C_DIM) {
        const int col = tid / C_DIM;
        const int cls = tid % C_DIM;
        const char* Bh = sb + OFF_B + (p * 2 + 0) * B_MAT;
        const char* Bl = Bh + B_MAT;
        const float* wpr = Wp + cls * H_DIM;
        float s = bp[cls];
        for (int k = 0; k < H_DIM; k++) {
            float h = __bfloat162float(*(const __nv_bfloat16*)(Bh + col * (KB * 2) + k * 2)) +
                      __bfloat162float(*(const __nv_bfloat16*)(Bl + col * (KB * 2) + k * 2));
            s = fmaf(wpr[k], h, s);
        }
        out[(col0 + col) * C_DIM + cls] = s;
    }
}

extern "C" void kernel_launch(void* const* d_in, const int* in_sizes, int n_in,
                              void* d_out, int out_size) {
    (void)in_sizes; (void)n_in; (void)out_size;
    const int*   x   = (const int*)  d_in[0];
    const float* emb = (const float*)d_in[1];
    const float* Wxg = (const float*)d_in[2];
    const float* Whg = (const float*)d_in[3];
    const float* bg  = (const float*)d_in[4];
    const float* Wxi = (const float*)d_in[5];
    const float* Whi = (const float*)d_in[6];
    const float* bi  = (const float*)d_in[7];
    const float* Wxf = (const float*)d_in[8];
    const float* Whf = (const float*)d_in[9];
    const float* bf  = (const float*)d_in[10];
    const float* Wxo = (const float*)d_in[11];
    const float* Who = (const float*)d_in[12];
    const float* bo  = (const float*)d_in[13];
    const float* Wp  = (const float*)d_in[14];
    const float* bp  = (const float*)d_in[15];
    float* out = (float*)d_out;

    cudaFuncSetAttribute(lstm_hmma_kernel,
                         cudaFuncAttributeMaxDynamicSharedMemorySize, SMEM_BYTES);
    lstm_hmma_kernel<<<(B_DIM / G_COLS) * CLUSTER, NTHREADS, SMEM_BYTES>>>(
        x, emb, Wxg, Whg, bg, Wxi, Whi, bi, Wxf, Whf, bf, Wxo, Who, bo, Wp, bp, out);
}

// round 7
// speedup vs baseline: 1.7746x; 1.2059x over previous
#include <cuda_runtime.h>
#include <cuda_bf16.h>
#include <cstdint>

#define T_SEQ   512
#define B_DIM   256
#define H_DIM   256
#define E_DIM   6
#define C_DIM   10
#define CLUSTER 8
#define G_COLS  16
#define NTHREADS 256
#define KC_N    17                  // 17 k-chunks of 16 -> K = 272

// B layout: per column, per k-pair (k=2kp,2kp+1): 8 bytes = [hi u32][lo u32]
// column stride 1184 B (296 words, ==8 mod 32 -> conflict-free paired LDS.64)
#define CSTRB   1184
#define B_MAT   (G_COLS * CSTRB)    // 18944 B per buffer
#define OFF_B    0                  // 2 buffers [p]
#define OFF_PART (2 * B_MAT)        // 37888 : 128 x 20 fp32
#define OFF_XB   (OFF_PART + 128 * 20 * 4)     // 48128 : x staged [t][col] int
#define OFF_EPK  (OFF_XB + T_SEQ * G_COLS * 4) // 80896 : emb split-packed u64[10][3]
#define SMEM_BYTES (OFF_EPK + 10 * 3 * 8 + 32) // 81168

__device__ __forceinline__ uint32_t smem_u32(const void* p) {
    return (uint32_t)__cvta_generic_to_shared(p);
}
__device__ __forceinline__ uint32_t mapa_rank(uint32_t addr, int r) {
    uint32_t ret;
    asm("mapa.shared::cluster.u32 %0, %1, %2;" : "=r"(ret) : "r"(addr), "r"(r));
    return ret;
}
__device__ __forceinline__ void st_cluster_u64(uint32_t addr, uint64_t v) {
    asm volatile("st.shared::cluster.u64 [%0], %1;" :: "r"(addr), "l"(v) : "memory");
}
__device__ __forceinline__ void cluster_sync_() {
    asm volatile("barrier.cluster.arrive.aligned;\n\tbarrier.cluster.wait.aligned;" ::: "memory");
}
__device__ __forceinline__ void mma16816(float c[4], const uint32_t a[4],
                                         uint32_t b0, uint32_t b1) {
    asm volatile("mma.sync.aligned.m16n8k16.row.col.f32.bf16.bf16.f32 "
                 "{%0,%1,%2,%3}, {%4,%5,%6,%7}, {%8,%9}, {%0,%1,%2,%3};"
                 : "+f"(c[0]), "+f"(c[1]), "+f"(c[2]), "+f"(c[3])
                 : "r"(a[0]), "r"(a[1]), "r"(a[2]), "r"(a[3]), "r"(b0), "r"(b1));
}
__device__ __forceinline__ uint32_t pack_hi(float a, float b) {
    __nv_bfloat162 t = __floats2bfloat162_rn(a, b);
    return *(uint32_t*)&t;
}
__device__ __forceinline__ void split2(float a, float b, uint32_t& hp, uint32_t& lp) {
    float ah = __bfloat162float(__float2bfloat16(a));
    float bh = __bfloat162float(__float2bfloat16(b));
    hp = pack_hi(ah, bh);
    lp = pack_hi(a - ah, b - bh);
}
__device__ __forceinline__ uint64_t mk64(uint32_t lo32, uint32_t hi32) {
    return ((uint64_t)hi32 << 32) | lo32;
}
__device__ __forceinline__ float sigf(float x)  { return __fdividef(1.0f, 1.0f + __expf(-x)); }
__device__ __forceinline__ float tanhf_(float x){ return __fdividef(2.0f, 1.0f + __expf(-2.0f * x)) - 1.0f; }

extern "C" __global__ void __launch_bounds__(NTHREADS, 1) __cluster_dims__(CLUSTER, 1, 1)
lstm_hmma_kernel(const int* __restrict__ x, const float* __restrict__ emb,
                 const float* __restrict__ Wxg, const float* __restrict__ Whg, const float* __restrict__ bg,
                 const float* __restrict__ Wxi, const float* __restrict__ Whi, const float* __restrict__ bi,
                 const float* __restrict__ Wxf, const float* __restrict__ Whf, const float* __restrict__ bf,
                 const float* __restrict__ Wxo, const float* __restrict__ Who, const float* __restrict__ bo,
                 const float* __restrict__ Wp,  const float* __restrict__ bp,
                 float* __restrict__ out)
{
    extern __shared__ char sb[];
    float*    part = (float*)(sb + OFF_PART);
    int*      xbuf = (int*)(sb + OFF_XB);
    uint64_t* epk  = (uint64_t*)(sb + OFF_EPK);
    const uint32_t sb32 = smem_u32(sb);

    const int tid  = threadIdx.x;
    const int wid  = tid >> 5;
    const int lane = tid & 31;
    const int g    = lane >> 2;       // groupID 0..7
    const int tg   = lane & 3;        // thread-in-group
    const int rank = blockIdx.x & (CLUSTER - 1);
    const int cid  = blockIdx.x / CLUSTER;
    const int col0 = cid * G_COLS;

    const float* WhTab[4] = { Whg, Whi, Whf, Who };
    const float* WxTab[4] = { Wxg, Wxi, Wxf, Wxo };
    const float* bTab[4]  = { bg,  bi,  bf,  bo  };

    // ---- A fragments, register-resident (hi/lo bf16 split) ----
    uint32_t aHi[KC_N][4], aLo[KC_N][4];
    {
        const int ra = 16 * wid + g;
        const int rb = ra + 8;
        auto getA = [&](int r, int k) -> float {
            int gate = r >> 5, j = r & 31;
            int row = rank * 32 + j;
            if (k < 256) return WhTab[gate][row * H_DIM + k];
            if (k < 260) return (k - 256 == gate) ? 1.0f : 0.0f;   // bias indicator
            if (k < 266) return WxTab[gate][row * E_DIM + (k - 260)];
            return 0.0f;
        };
        #pragma unroll
        for (int kc = 0; kc < KC_N; kc++) {
            const int k0 = kc * 16 + 2 * tg;
            split2(getA(ra, k0),     getA(ra, k0 + 1), aHi[kc][0], aLo[kc][0]);
            split2(getA(rb, k0),     getA(rb, k0 + 1), aHi[kc][1], aLo[kc][1]);
            split2(getA(ra, k0 + 8), getA(ra, k0 + 9), aHi[kc][2], aLo[kc][2]);
            split2(getA(rb, k0 + 8), getA(rb, k0 + 9), aHi[kc][3], aLo[kc][3]);
        }
    }

    // ---- zero both B buffers (h0 = 0, pads) ----
    for (int i = tid; i < (2 * B_MAT) / 4; i += NTHREADS)
        ((uint32_t*)(sb + OFF_B))[i] = 0u;

    // ---- stage x sequence: xbuf[t][col] ----
    for (int i = tid; i < G_COLS * T_SEQ; i += NTHREADS) {
        int c = i >> 9, t = i & 511;
        xbuf[t * G_COLS + c] = x[(col0 + c) * T_SEQ + t];
    }
    // ---- emb table pre-split: epk[v][pe] = {hi-pair, lo-pair} ----
    if (tid < 10 * 3) {
        int v = tid / 3, pe = tid % 3;
        uint32_t hp, lp;
        split2(emb[v * E_DIM + 2 * pe], emb[v * E_DIM + 2 * pe + 1], hp, lp);
        epk[v * 3 + pe] = mk64(hp, lp);
    }
    __syncthreads();

    // ---- bias k-pairs (kp 128,129) both buffers; emb(t=0) (kp 130..132) buf 0 ----
    if (tid < G_COLS) {
        const int col = tid;
        uint32_t h01, l01, h23, l23;
        split2(bTab[0][col0 + col], bTab[1][col0 + col], h01, l01);
        split2(bTab[2][col0 + col], bTab[3][col0 + col], h23, l23);
        #pragma unroll
        for (int pb = 0; pb < 2; pb++) {
            char* Bc = sb + OFF_B + pb * B_MAT + col * CSTRB;
            *(uint64_t*)(Bc + 128 * 8) = mk64(h01, l01);
            *(uint64_t*)(Bc + 129 * 8) = mk64(h23, l23);
        }
        int xi = xbuf[0 * G_COLS + col];
        char* B0 = sb + OFF_B + col * CSTRB;
        #pragma unroll
        for (int pe = 0; pe < 3; pe++)
            *(uint64_t*)(B0 + (130 + pe) * 8) = epk[xi * 3 + pe];
    }

    uint32_t peer[CLUSTER];
    #pragma unroll
    for (int r = 0; r < CLUSTER; r++) peer[r] = mapa_rank(sb32, r);

    __syncthreads();
    cluster_sync_();

    // finalize mapping: thread -> rows (2fj, 2fj+1), column fcl
    const int fj  = tid >> 4;        // 0..15
    const int fcl = tid & 15;        // 0..15
    float cst0 = 0.0f, cst1 = 0.0f;

    const int coff0 = g * CSTRB;           // n-tile 0 column
    const int coff1 = (8 + g) * CSTRB;     // n-tile 1 column

    int p = 0;
    for (int t = 0; t < T_SEQ; t++) {
        const char* Bp = sb + OFF_B + p * B_MAT;

        // ---- 3 independent accumulation chains per n-tile ----
        float aHH0[4] = {0,0,0,0}, aLH0[4] = {0,0,0,0}, aHL0[4] = {0,0,0,0};
        float aHH1[4] = {0,0,0,0}, aLH1[4] = {0,0,0,0}, aHL1[4] = {0,0,0,0};

        #pragma unroll
        for (int kc = 0; kc < KC_N; kc++) {
            const uint32_t kb = (uint32_t)(8 * kc + tg) * 8;
            uint2 B00 = *(const uint2*)(Bp + coff0 + kb);        // {hi,lo} k-pair
            uint2 B01 = *(const uint2*)(Bp + coff0 + kb + 32);   // k+8 pair
            uint2 B10 = *(const uint2*)(Bp + coff1 + kb);
            uint2 B11 = *(const uint2*)(Bp + coff1 + kb + 32);
            mma16816(aHH0, aHi[kc], B00.x, B01.x);
            mma16816(aLH0, aLo[kc], B00.x, B01.x);
            mma16816(aHL0, aHi[kc], B00.y, B01.y);
            mma16816(aHH1, aHi[kc], B10.x, B11.x);
            mma16816(aLH1, aLo[kc], B10.x, B11.x);
            mma16816(aHL1, aHi[kc], B10.y, B11.y);
        }

        // ---- combine + store D tiles to part[row][col], stride 20 ----
        {
            float* pr0 = part + (16 * wid + g) * 20;
            float* pr1 = pr0 + 8 * 20;
            *(float2*)(pr0 + 2 * tg)     = make_float2(aHH0[0] + aLH0[0] + aHL0[0],
                                                       aHH0[1] + aLH0[1] + aHL0[1]);
            *(float2*)(pr1 + 2 * tg)     = make_float2(aHH0[2] + aLH0[2] + aHL0[2],
                                                       aHH0[3] + aLH0[3] + aHL0[3]);
            *(float2*)(pr0 + 8 + 2 * tg) = make_float2(aHH1[0] + aLH1[0] + aHL1[0],
                                                       aHH1[1] + aLH1[1] + aHL1[1]);
            *(float2*)(pr1 + 8 + 2 * tg) = make_float2(aHH1[2] + aLH1[2] + aHL1[2],
                                                       aHH1[3] + aLH1[3] + aHL1[3]);
        }
        __syncthreads();

        // ---- next-step embedding into local B[p^1] (smem-only, no LDG) ----
        if (tid < G_COLS && t + 1 < T_SEQ) {
            int xi = xbuf[(t + 1) * G_COLS + tid];
            char* Bn = sb + OFF_B + (p ^ 1) * B_MAT + tid * CSTRB;
            const uint64_t* ep = epk + xi * 3;
            *(uint64_t*)(Bn + 130 * 8) = ep[0];
            *(uint64_t*)(Bn + 131 * 8) = ep[1];
            *(uint64_t*)(Bn + 132 * 8) = ep[2];
        }

        // ---- finalize: gates + c/h update for rows 2fj, 2fj+1, col fcl ----
        float pre0[4], pre1[4];
        #pragma unroll
        for (int q = 0; q < 4; q++) {
            pre0[q] = part[(q * 32 + 2 * fj)     * 20 + fcl];
            pre1[q] = part[(q * 32 + 2 * fj + 1) * 20 + fcl];
        }
        float g0 = tanhf_(pre0[0]), i0 = sigf(pre0[1]), f0 = sigf(pre0[2]), o0 = sigf(pre0[3]);
        float g1 = tanhf_(pre1[0]), i1 = sigf(pre1[1]), f1 = sigf(pre1[2]), o1 = sigf(pre1[3]);
        cst0 = fmaf(g0, i0, cst0 * f0);
        cst1 = fmaf(g1, i1, cst1 * f1);
        const float hn0 = tanhf_(cst0) * o0;
        const float hn1 = tanhf_(cst1) * o1;

        uint32_t hp, lp;
        split2(hn0, hn1, hp, lp);
        const uint64_t pkt = mk64(hp, lp);

        // ---- broadcast h k-pair (kp = rank*16 + fj) to all peers' B[p^1] ----
        const uint32_t ohi = (uint32_t)(OFF_B + (p ^ 1) * B_MAT +
                                        fcl * CSTRB + (rank * 16 + fj) * 8);
        #pragma unroll
        for (int r = 0; r < CLUSTER; r++)
            st_cluster_u64(peer[r] + ohi, pkt);

        cluster_sync_();
        p ^= 1;
    }

    // ---- projection: out[b, c] = sum_k Wp[c,k] h[k,b] + bp[c] ----
    if (rank == 0 && tid < G_COLS * C_DIM) {
        const int col = tid / C_DIM;
        const int cls = tid % C_DIM;
        const char* Bc = sb + OFF_B + p * B_MAT + col * CSTRB;
        const float* wpr = Wp + cls * H_DIM;
        float s = bp[cls];
        for (int kp = 0; kp < H_DIM / 2; kp++) {
            uint64_t w = *(const uint64_t*)(Bc + kp * 8);
            uint32_t hiw = (uint32_t)w, low = (uint32_t)(w >> 32);
            __nv_bfloat162 hv = *(__nv_bfloat162*)&hiw;
            __nv_bfloat162 lv = *(__nv_bfloat162*)&low;
            float h0 = __bfloat162float(hv.x) + __bfloat162float(lv.x);
            float h1 = __bfloat162float(hv.y) + __bfloat162float(lv.y);
            s = fmaf(wpr[2 * kp], h0, fmaf(wpr[2 * kp + 1], h1, s));
        }
        out[(col0 + col) * C_DIM + cls] = s;
    }
}

extern "C" void kernel_launch(void* const* d_in, const int* in_sizes, int n_in,
                              void* d_out, int out_size) {
    (void)in_sizes; (void)n_in; (void)out_size;
    const int*   x   = (const int*)  d_in[0];
    const float* emb = (const float*)d_in[1];
    const float* Wxg = (const float*)d_in[2];
    const float* Whg = (const float*)d_in[3];
    const float* bg  = (const float*)d_in[4];
    const float* Wxi = (const float*)d_in[5];
    const float* Whi = (const float*)d_in[6];
    const float* bi  = (const float*)d_in[7];
    const float* Wxf = (const float*)d_in[8];
    const float* Whf = (const float*)d_in[9];
    const float* bf  = (const float*)d_in[10];
    const float* Wxo = (const float*)d_in[11];
    const float* Who = (const float*)d_in[12];
    const float* bo  = (const float*)d_in[13];
    const float* Wp  = (const float*)d_in[14];
    const float* bp  = (const float*)d_in[15];
    float* out = (float*)d_out;

    cudaFuncSetAttribute(lstm_hmma_kernel,
                         cudaFuncAttributeMaxDynamicSharedMemorySize, SMEM_BYTES);
    lstm_hmma_kernel<<<(B_DIM / G_COLS) * CLUSTER, NTHREADS, SMEM_BYTES>>>(
        x, emb, Wxg, Whg, bg, Wxi, Whi, bi, Wxf, Whf, bf, Wxo, Who, bo, Wp, bp, out);
}

// round 9
// speedup vs baseline: 1.8732x; 1.0556x over previous
#include <cuda_runtime.h>
#include <cuda_bf16.h>
#include <cstdint>

#define T_SEQ   512
#define B_DIM   256
#define H_DIM   256
#define E_DIM   6
#define C_DIM   10
#define CLUSTER 8
#define G_COLS  16
#define NTHREADS 256
#define KC_N    17                  // 17 k-chunks of 16 -> K = 272

// B layout: per column, per k-pair kp: u64 = [hi bf16x2][lo bf16x2]
// column stride 1184 B (296 words, ==8 mod 32 -> conflict-free paired LDS.64)
// kp slots: 0..127 = h, 128..129 = bias, 130..132 = embedding
#define CSTRB   1184
#define B_MAT   (G_COLS * CSTRB)                 // 18944 B per buffer
#define OFF_B    0                               // 2 ping-pong buffers
#define OFF_XB   (2 * B_MAT)                     // 37888 : x staged [t][col]
#define OFF_EPK  (OFF_XB + T_SEQ * G_COLS * 4)   // 70656 : emb split u64[10][3]
#define SMEM_BYTES (OFF_EPK + 240 + 16)

__device__ __forceinline__ uint32_t smem_u32(const void* p) {
    return (uint32_t)__cvta_generic_to_shared(p);
}
__device__ __forceinline__ uint32_t mapa_rank(uint32_t addr, int r) {
    uint32_t ret;
    asm("mapa.shared::cluster.u32 %0, %1, %2;" : "=r"(ret) : "r"(addr), "r"(r));
    return ret;
}
__device__ __forceinline__ void st_cluster_u64(uint32_t addr, uint64_t v) {
    asm volatile("st.shared::cluster.u64 [%0], %1;" :: "r"(addr), "l"(v) : "memory");
}
__device__ __forceinline__ void cluster_sync_() {
    asm volatile("barrier.cluster.arrive.aligned;\n\tbarrier.cluster.wait.aligned;" ::: "memory");
}
__device__ __forceinline__ void mma16816(float c[4], const uint32_t a[4],
                                         uint32_t b0, uint32_t b1) {
    asm volatile("mma.sync.aligned.m16n8k16.row.col.f32.bf16.bf16.f32 "
                 "{%0,%1,%2,%3}, {%4,%5,%6,%7}, {%8,%9}, {%0,%1,%2,%3};"
                 : "+f"(c[0]), "+f"(c[1]), "+f"(c[2]), "+f"(c[3])
                 : "r"(a[0]), "r"(a[1]), "r"(a[2]), "r"(a[3]), "r"(b0), "r"(b1));
}
__device__ __forceinline__ uint32_t pack_hi(float a, float b) {
    __nv_bfloat162 t = __floats2bfloat162_rn(a, b);
    return *(uint32_t*)&t;
}
__device__ __forceinline__ void split2(float a, float b, uint32_t& hp, uint32_t& lp) {
    float ah = __bfloat162float(__float2bfloat16(a));
    float bh = __bfloat162float(__float2bfloat16(b));
    hp = pack_hi(ah, bh);
    lp = pack_hi(a - ah, b - bh);
}
__device__ __forceinline__ uint64_t mk64(uint32_t lo32, uint32_t hi32) {
    return ((uint64_t)hi32 << 32) | lo32;
}
__device__ __forceinline__ float sigf(float x)  { return __fdividef(1.0f, 1.0f + __expf(-x)); }
__device__ __forceinline__ float tanhf_(float x){ return __fdividef(2.0f, 1.0f + __expf(-2.0f * x)) - 1.0f; }

extern "C" __global__ void __launch_bounds__(NTHREADS, 1) __cluster_dims__(CLUSTER, 1, 1)
lstm_hmma_kernel(const int* __restrict__ x, const float* __restrict__ emb,
                 const float* __restrict__ Wxg, const float* __restrict__ Whg, const float* __restrict__ bg,
                 const float* __restrict__ Wxi, const float* __restrict__ Whi, const float* __restrict__ bi,
                 const float* __restrict__ Wxf, const float* __restrict__ Whf, const float* __restrict__ bf,
                 const float* __restrict__ Wxo, const float* __restrict__ Who, const float* __restrict__ bo,
                 const float* __restrict__ Wp,  const float* __restrict__ bp,
                 float* __restrict__ out)
{
    extern __shared__ char sb[];
    int*      xbuf = (int*)(sb + OFF_XB);
    uint64_t* epk  = (uint64_t*)(sb + OFF_EPK);
    const uint32_t sb32 = smem_u32(sb);

    const int tid  = threadIdx.x;
    const int wid  = tid >> 5;
    const int lane = tid & 31;
    const int g    = lane >> 2;       // groupID 0..7
    const int tg   = lane & 3;        // thread-in-group
    const int qa   = g >> 2;          // gate-pair selector (0: gates {0,2}, 1: gates {1,3})
    const int rank = blockIdx.x & (CLUSTER - 1);
    const int cid  = blockIdx.x / CLUSTER;
    const int col0 = cid * G_COLS;

    const float* WhTab[4] = { Whg, Whi, Whf, Who };
    const float* WxTab[4] = { Wxg, Wxi, Wxf, Wxo };
    const float* bTab[4]  = { bg,  bi,  bf,  bo  };

    // ---- A fragments, register-resident, remapped rows ----
    // warp tile row r (0..15): gate = r>>2, j = 4*wid + (r&3)
    uint32_t aHi[KC_N][4], aLo[KC_N][4];
    {
        auto getA = [&](int r, int k) -> float {
            int gate = r >> 2, j = 4 * wid + (r & 3);
            int row = rank * 32 + j;
            if (k < 256) return WhTab[gate][row * H_DIM + k];
            if (k < 260) return (k - 256 == gate) ? 1.0f : 0.0f;   // bias indicator
            if (k < 266) return WxTab[gate][row * E_DIM + (k - 260)];
            return 0.0f;
        };
        const int ra = g, rb = g + 8;
        #pragma unroll
        for (int kc = 0; kc < KC_N; kc++) {
            const int k0 = kc * 16 + 2 * tg;
            split2(getA(ra, k0),     getA(ra, k0 + 1), aHi[kc][0], aLo[kc][0]);
            split2(getA(rb, k0),     getA(rb, k0 + 1), aHi[kc][1], aLo[kc][1]);
            split2(getA(ra, k0 + 8), getA(ra, k0 + 9), aHi[kc][2], aLo[kc][2]);
            split2(getA(rb, k0 + 8), getA(rb, k0 + 9), aHi[kc][3], aLo[kc][3]);
        }
    }

    // ---- zero both B buffers (h0 = 0, pads) ----
    for (int i = tid; i < (2 * B_MAT) / 4; i += NTHREADS)
        ((uint32_t*)(sb + OFF_B))[i] = 0u;
    // ---- stage x sequence ----
    for (int i = tid; i < G_COLS * T_SEQ; i += NTHREADS) {
        int c = i >> 9, t = i & 511;
        xbuf[t * G_COLS + c] = x[(col0 + c) * T_SEQ + t];
    }
    // ---- emb table pre-split ----
    if (tid < 10 * 3) {
        int v = tid / 3, pe = tid % 3;
        uint32_t hp, lp;
        split2(emb[v * E_DIM + 2 * pe], emb[v * E_DIM + 2 * pe + 1], hp, lp);
        epk[v * 3 + pe] = mk64(hp, lp);
    }
    __syncthreads();

    // ---- bias (both buffers) + emb(t=0) into buffer 0 ----
    if (tid < G_COLS) {
        const int col = tid;
        uint32_t h01, l01, h23, l23;
        split2(bTab[0][col0 + col], bTab[1][col0 + col], h01, l01);
        split2(bTab[2][col0 + col], bTab[3][col0 + col], h23, l23);
        #pragma unroll
        for (int pb = 0; pb < 2; pb++) {
            char* Bc = sb + OFF_B + pb * B_MAT + col * CSTRB;
            *(uint64_t*)(Bc + 128 * 8) = mk64(h01, l01);
            *(uint64_t*)(Bc + 129 * 8) = mk64(h23, l23);
        }
        int xi = xbuf[col];
        char* B0 = sb + OFF_B + col * CSTRB;
        *(uint64_t*)(B0 + 130 * 8) = epk[xi * 3 + 0];
        *(uint64_t*)(B0 + 131 * 8) = epk[xi * 3 + 1];
        *(uint64_t*)(B0 + 132 * 8) = epk[xi * 3 + 2];
    }

    uint32_t peer[CLUSTER];
    #pragma unroll
    for (int r = 0; r < CLUSTER; r++) peer[r] = mapa_rank(sb32, r);

    __syncthreads();
    cluster_sync_();

    // thread-owned output mapping (j = 4*wid + (g&3))
    const int cA   = 2 * tg + qa;                // owned column, n-tile 0
    const int cB   = cA + 8;                     // owned column, n-tile 1
    const int jlow = ((g & 1) == 0);             // owns even j
    const int kpl  = 2 * wid + ((g & 3) >> 1);   // local k-pair index (j>>1)
    const uint32_t stCol = (uint32_t)((jlow ? cA : cB) * CSTRB + (rank * 16 + kpl) * 8);
    float cst0 = 0.0f, cst1 = 0.0f;

    const int coff0 = g * CSTRB, coff1 = (8 + g) * CSTRB;

    int p = 0;
    for (int t = 0; t < T_SEQ; t++) {
        const char* Bp = sb + OFF_B + p * B_MAT;

        // ---- MMA: 3 independent chains x 2 n-tiles ----
        float hh0[4] = {0,0,0,0}, lh0[4] = {0,0,0,0}, hl0[4] = {0,0,0,0};
        float hh1[4] = {0,0,0,0}, lh1[4] = {0,0,0,0}, hl1[4] = {0,0,0,0};
        #pragma unroll
        for (int kc = 0; kc < KC_N; kc++) {
            const uint32_t kb = (uint32_t)(8 * kc + tg) * 8;
            uint2 B00 = *(const uint2*)(Bp + coff0 + kb);
            uint2 B01 = *(const uint2*)(Bp + coff0 + kb + 32);
            uint2 B10 = *(const uint2*)(Bp + coff1 + kb);
            uint2 B11 = *(const uint2*)(Bp + coff1 + kb + 32);
            mma16816(hh0, aHi[kc], B00.x, B01.x);
            mma16816(lh0, aLo[kc], B00.x, B01.x);
            mma16816(hl0, aHi[kc], B00.y, B01.y);
            mma16816(hh1, aHi[kc], B10.x, B11.x);
            mma16816(lh1, aLo[kc], B10.x, B11.x);
            mma16816(hl1, aHi[kc], B10.y, B11.y);
        }
        // d-frag: c0=(row g, col 2tg) c1=(row g, 2tg+1) c2=(row g+8, 2tg) c3=(row g+8, 2tg+1)
        // row g -> gate qa; row g+8 -> gate qa+2; same j.
        float d0n0 = hh0[0] + lh0[0] + hl0[0];
        float d1n0 = hh0[1] + lh0[1] + hl0[1];
        float d2n0 = hh0[2] + lh0[2] + hl0[2];
        float d3n0 = hh0[3] + lh0[3] + hl0[3];
        float d0n1 = hh1[0] + lh1[0] + hl1[0];
        float d1n1 = hh1[1] + lh1[1] + hl1[1];
        float d2n1 = hh1[2] + lh1[2] + hl1[2];
        float d3n1 = hh1[3] + lh1[3] + hl1[3];

        // ---- gate exchange with lane^16 (same j, other gate-pair) ----
        float sA0 = qa ? d0n0 : d1n0;
        float rA0 = __shfl_xor_sync(0xffffffffu, sA0, 16);
        float sB0 = qa ? d2n0 : d3n0;
        float rB0 = __shfl_xor_sync(0xffffffffu, sB0, 16);
        float pg00 = qa ? rA0 : d0n0;   // gate0 @ (j, cA)
        float pg10 = qa ? d1n0 : rA0;   // gate1
        float pg20 = qa ? rB0 : d2n0;   // gate2
        float pg30 = qa ? d3n0 : rB0;   // gate3

        float sA1 = qa ? d0n1 : d1n1;
        float rA1 = __shfl_xor_sync(0xffffffffu, sA1, 16);
        float sB1 = qa ? d2n1 : d3n1;
        float rB1 = __shfl_xor_sync(0xffffffffu, sB1, 16);
        float pg01 = qa ? rA1 : d0n1;
        float pg11 = qa ? d1n1 : rA1;
        float pg21 = qa ? rB1 : d2n1;
        float pg31 = qa ? d3n1 : rB1;

        // ---- activations + c/h update ((j,cA) and (j,cB)) ----
        float g0 = tanhf_(pg00), i0 = sigf(pg10), f0 = sigf(pg20), o0 = sigf(pg30);
        float g1 = tanhf_(pg01), i1 = sigf(pg11), f1 = sigf(pg21), o1 = sigf(pg31);
        cst0 = fmaf(g0, i0, cst0 * f0);
        cst1 = fmaf(g1, i1, cst1 * f1);
        const float h0v = tanhf_(cst0) * o0;
        const float h1v = tanhf_(cst1) * o1;

        // ---- j-pair exchange with lane^4: (even j, odd j) same col ----
        float o0v = __shfl_xor_sync(0xffffffffu, h0v, 4);
        float o1v = __shfl_xor_sync(0xffffffffu, h1v, 4);
        float va = jlow ? h0v : o1v;    // k even
        float vb = jlow ? o0v : h1v;    // k odd
        uint32_t hp, lp;
        split2(va, vb, hp, lp);
        const uint64_t pkt = mk64(hp, lp);

        // ---- broadcast h k-pair to all 8 CTAs' buffer p^1 ----
        const uint32_t dOff = (uint32_t)(OFF_B + (p ^ 1) * B_MAT) + stCol;
        #pragma unroll
        for (int r = 0; r < CLUSTER; r++)
            st_cluster_u64(peer[r] + dOff, pkt);

        // ---- next-step embedding into own buffer p^1 (plain STS) ----
        if (tid < G_COLS && t + 1 < T_SEQ) {
            int xi = xbuf[(t + 1) * G_COLS + tid];
            char* Bn = sb + OFF_B + (p ^ 1) * B_MAT + tid * CSTRB;
            *(uint64_t*)(Bn + 130 * 8) = epk[xi * 3 + 0];
            *(uint64_t*)(Bn + 131 * 8) = epk[xi * 3 + 1];
            *(uint64_t*)(Bn + 132 * 8) = epk[xi * 3 + 2];
        }

        cluster_sync_();     // read-completion + write-visibility rendezvous
        p ^= 1;
    }

    // ---- projection: out[b, c] = sum_k Wp[c,k] h[k,b] + bp[c] (final h in buffer p) ----
    if (rank == 0 && tid < G_COLS * C_DIM) {
        const int col = tid / C_DIM;
        const int cls = tid % C_DIM;
        const char* Bc = sb + OFF_B + p * B_MAT + col * CSTRB;
        const float* wpr = Wp + cls * H_DIM;
        float s = bp[cls];
        for (int kp = 0; kp < H_DIM / 2; kp++) {
            uint64_t w = *(const uint64_t*)(Bc + kp * 8);
            uint32_t hiw = (uint32_t)w, low = (uint32_t)(w >> 32);
            __nv_bfloat162 hv = *(__nv_bfloat162*)&hiw;
            __nv_bfloat162 lv = *(__nv_bfloat162*)&low;
            float e0 = __bfloat162float(hv.x) + __bfloat162float(lv.x);
            float e1 = __bfloat162float(hv.y) + __bfloat162float(lv.y);
            s = fmaf(wpr[2 * kp], e0, fmaf(wpr[2 * kp + 1], e1, s));
        }
        out[(col0 + col) * C_DIM + cls] = s;
    }
}

extern "C" void kernel_launch(void* const* d_in, const int* in_sizes, int n_in,
                              void* d_out, int out_size) {
    (void)in_sizes; (void)n_in; (void)out_size;
    const int*   x   = (const int*)  d_in[0];
    const float* emb = (const float*)d_in[1];
    const float* Wxg = (const float*)d_in[2];
    const float* Whg = (const float*)d_in[3];
    const float* bg  = (const float*)d_in[4];
    const float* Wxi = (const float*)d_in[5];
    const float* Whi = (const float*)d_in[6];
    const float* bi  = (const float*)d_in[7];
    const float* Wxf = (const float*)d_in[8];
    const float* Whf = (const float*)d_in[9];
    const float* bf  = (const float*)d_in[10];
    const float* Wxo = (const float*)d_in[11];
    const float* Who = (const float*)d_in[12];
    const float* bo  = (const float*)d_in[13];
    const float* Wp  = (const float*)d_in[14];
    const float* bp  = (const float*)d_in[15];
    float* out = (float*)d_out;

    cudaFuncSetAttribute(lstm_hmma_kernel,
                         cudaFuncAttributeMaxDynamicSharedMemorySize, SMEM_BYTES);
    lstm_hmma_kernel<<<(B_DIM / G_COLS) * CLUSTER, NTHREADS, SMEM_BYTES>>>(
        x, emb, Wxg, Whg, bg, Wxi, Whi, bi, Wxf, Whf, bf, Wxo, Who, bo, Wp, bp, out);
}

// round 10
// speedup vs baseline: 2.2468x; 1.1994x over previous
#include <cuda_runtime.h>
#include <cuda_fp16.h>
#include <cstdint>

#define T_SEQ   512
#define B_DIM   256
#define H_DIM   256
#define E_DIM   6
#define C_DIM   10
#define CLUSTER 8
#define G_COLS  16
#define NTHREADS 256
#define KC_N    17                  // 17 k-chunks of 16 -> K = 272

// B-hi: per column 164 words (656B), fp16x2 per k-pair kp (0..135).
//   kp 0..127 = h, 128..129 = bias, 130..132 = emb, 133..135 = pad
//   stride 164 = 4 (mod 32) -> conflict-free LDS.32 across (g, tg)
// B-lo: per column 8 words, slots = kp-128 (bias/emb lo only)
#define SHI_W   164
#define BH_MAT  (G_COLS * SHI_W * 4)             // 10496 B
#define BL_MAT  (G_COLS * 8 * 4)                 // 512 B
#define OFF_BH   0                               // 2 buffers
#define OFF_BL   (2 * BH_MAT)                    // 20992, 2 buffers
#define OFF_XB   (OFF_BL + 2 * BL_MAT)           // 22016 : x staged [t][col]
#define OFF_EPK  (OFF_XB + T_SEQ * G_COLS * 4)   // 54784 : emb u32[10][6] (hi3, lo3)
#define SMEM_BYTES (OFF_EPK + 240 + 16)

__device__ __forceinline__ uint32_t smem_u32(const void* p) {
    return (uint32_t)__cvta_generic_to_shared(p);
}
__device__ __forceinline__ uint32_t mapa_rank(uint32_t addr, int r) {
    uint32_t ret;
    asm("mapa.shared::cluster.u32 %0, %1, %2;" : "=r"(ret) : "r"(addr), "r"(r));
    return ret;
}
__device__ __forceinline__ void st_cluster_u32(uint32_t addr, uint32_t v) {
    asm volatile("st.shared::cluster.u32 [%0], %1;" :: "r"(addr), "r"(v) : "memory");
}
__device__ __forceinline__ void cluster_sync_() {
    asm volatile("barrier.cluster.arrive.aligned;\n\tbarrier.cluster.wait.aligned;" ::: "memory");
}
__device__ __forceinline__ void mma16816h(float c[4], const uint32_t a[4],
                                          uint32_t b0, uint32_t b1) {
    asm volatile("mma.sync.aligned.m16n8k16.row.col.f32.f16.f16.f32 "
                 "{%0,%1,%2,%3}, {%4,%5,%6,%7}, {%8,%9}, {%0,%1,%2,%3};"
                 : "+f"(c[0]), "+f"(c[1]), "+f"(c[2]), "+f"(c[3])
                 : "r"(a[0]), "r"(a[1]), "r"(a[2]), "r"(a[3]), "r"(b0), "r"(b1));
}
__device__ __forceinline__ uint32_t pack_h2(float a, float b) {
    __half2 t = __floats2half2_rn(a, b);
    return *(uint32_t*)&t;
}
__device__ __forceinline__ void split2h(float a, float b, uint32_t& hp, uint32_t& lp) {
    float ah = __half2float(__float2half_rn(a));
    float bh = __half2float(__float2half_rn(b));
    hp = pack_h2(ah, bh);
    lp = pack_h2(a - ah, b - bh);
}
__device__ __forceinline__ float tanhapx(float x) {
    float y;
    asm("tanh.approx.f32 %0, %1;" : "=f"(y) : "f"(x));
    return y;
}
__device__ __forceinline__ float sigapx(float x) {
    return fmaf(0.5f, tanhapx(0.5f * x), 0.5f);
}

extern "C" __global__ void __launch_bounds__(NTHREADS, 1) __cluster_dims__(CLUSTER, 1, 1)
lstm_hmma_kernel(const int* __restrict__ x, const float* __restrict__ emb,
                 const float* __restrict__ Wxg, const float* __restrict__ Whg, const float* __restrict__ bg,
                 const float* __restrict__ Wxi, const float* __restrict__ Whi, const float* __restrict__ bi,
                 const float* __restrict__ Wxf, const float* __restrict__ Whf, const float* __restrict__ bf,
                 const float* __restrict__ Wxo, const float* __restrict__ Who, const float* __restrict__ bo,
                 const float* __restrict__ Wp,  const float* __restrict__ bp,
                 float* __restrict__ out)
{
    extern __shared__ char sb[];
    int*      xbuf = (int*)(sb + OFF_XB);
    uint32_t* epk  = (uint32_t*)(sb + OFF_EPK);
    const uint32_t sb32 = smem_u32(sb);

    const int tid  = threadIdx.x;
    const int wid  = tid >> 5;
    const int lane = tid & 31;
    const int g    = lane >> 2;       // groupID 0..7
    const int tg   = lane & 3;        // thread-in-group
    const int qa   = g >> 2;          // gate-pair selector
    const int rank = blockIdx.x & (CLUSTER - 1);
    const int cid  = blockIdx.x / CLUSTER;
    const int col0 = cid * G_COLS;

    const float* WhTab[4] = { Whg, Whi, Whf, Who };
    const float* WxTab[4] = { Wxg, Wxi, Wxf, Wxo };
    const float* bTab[4]  = { bg,  bi,  bf,  bo  };

    // ---- A fragments, register-resident fp16 hi/lo, remapped rows ----
    // warp tile row r (0..15): gate = r>>2, j = 4*wid + (r&3)
    uint32_t aHi[KC_N][4], aLo[KC_N][4];
    {
        auto getA = [&](int r, int k) -> float {
            int gate = r >> 2, j = 4 * wid + (r & 3);
            int row = rank * 32 + j;
            if (k < 256) return WhTab[gate][row * H_DIM + k];
            if (k < 260) return (k - 256 == gate) ? 1.0f : 0.0f;   // bias indicator
            if (k < 266) return WxTab[gate][row * E_DIM + (k - 260)];
            return 0.0f;
        };
        const int ra = g, rb = g + 8;
        #pragma unroll
        for (int kc = 0; kc < KC_N; kc++) {
            const int k0 = kc * 16 + 2 * tg;
            split2h(getA(ra, k0),     getA(ra, k0 + 1), aHi[kc][0], aLo[kc][0]);
            split2h(getA(rb, k0),     getA(rb, k0 + 1), aHi[kc][1], aLo[kc][1]);
            split2h(getA(ra, k0 + 8), getA(ra, k0 + 9), aHi[kc][2], aLo[kc][2]);
            split2h(getA(rb, k0 + 8), getA(rb, k0 + 9), aHi[kc][3], aLo[kc][3]);
        }
    }

    // ---- zero B-hi / B-lo buffers (h0 = 0, pads) ----
    for (int i = tid; i < (2 * BH_MAT + 2 * BL_MAT) / 4; i += NTHREADS)
        ((uint32_t*)(sb + OFF_BH))[i] = 0u;
    // ---- stage x sequence ----
    for (int i = tid; i < G_COLS * T_SEQ; i += NTHREADS) {
        int c = i >> 9, t = i & 511;
        xbuf[t * G_COLS + c] = x[(col0 + c) * T_SEQ + t];
    }
    // ---- emb table pre-split: [v][0..2]=hi pairs, [3..5]=lo pairs ----
    if (tid < 10 * 3) {
        int v = tid / 3, pe = tid % 3;
        uint32_t hp, lp;
        split2h(emb[v * E_DIM + 2 * pe], emb[v * E_DIM + 2 * pe + 1], hp, lp);
        epk[v * 6 + pe]     = hp;
        epk[v * 6 + 3 + pe] = lp;
    }
    __syncthreads();

    // ---- bias (both buffers) + emb(t=0) into buffer 0 ----
    if (tid < G_COLS) {
        const int col = tid;
        uint32_t h01, l01, h23, l23;
        split2h(bTab[0][col0 + col], bTab[1][col0 + col], h01, l01);
        split2h(bTab[2][col0 + col], bTab[3][col0 + col], h23, l23);
        #pragma unroll
        for (int pb = 0; pb < 2; pb++) {
            uint32_t* Bh = (uint32_t*)(sb + OFF_BH + pb * BH_MAT) + col * SHI_W;
            uint32_t* Bl = (uint32_t*)(sb + OFF_BL + pb * BL_MAT) + col * 8;
            Bh[128] = h01;  Bh[129] = h23;
            Bl[0]   = l01;  Bl[1]   = l23;
        }
        int xi = xbuf[col];
        uint32_t* Bh = (uint32_t*)(sb + OFF_BH) + col * SHI_W;
        uint32_t* Bl = (uint32_t*)(sb + OFF_BL) + col * 8;
        #pragma unroll
        for (int pe = 0; pe < 3; pe++) {
            Bh[130 + pe] = epk[xi * 6 + pe];
            Bl[2 + pe]   = epk[xi * 6 + 3 + pe];
        }
    }

    uint32_t peer[CLUSTER];
    #pragma unroll
    for (int r = 0; r < CLUSTER; r++) peer[r] = mapa_rank(sb32, r);

    __syncthreads();
    cluster_sync_();

    // thread-owned output mapping (j = 4*wid + (g&3))
    const int cA   = 2 * tg + qa;
    const int cB   = cA + 8;
    const int jlow = ((g & 1) == 0);
    const int kpl  = 2 * wid + ((g & 3) >> 1);
    const uint32_t stCol = (uint32_t)(((jlow ? cA : cB) * SHI_W + rank * 16 + kpl) * 4);
    float cst0 = 0.0f, cst1 = 0.0f;

    const uint32_t coff0 = (uint32_t)(g * SHI_W * 4);
    const uint32_t coff1 = (uint32_t)((8 + g) * SHI_W * 4);
    const uint32_t loff0 = (uint32_t)(g * 32);
    const uint32_t loff1 = (uint32_t)((8 + g) * 32);

    int p = 0;
    for (int t = 0; t < T_SEQ; t++) {
        const char* Bh = sb + OFF_BH + p * BH_MAT;
        const char* Bl = sb + OFF_BL + p * BL_MAT;

        // ---- MMA: hi*hi + lo*hi (17 chunks) + hi*lo (chunk 16 only) ----
        float hh0[4] = {0,0,0,0}, lh0[4] = {0,0,0,0};
        float hh1[4] = {0,0,0,0}, lh1[4] = {0,0,0,0};
        #pragma unroll
        for (int kc = 0; kc < KC_N; kc++) {
            const uint32_t kb = (uint32_t)(8 * kc + tg) * 4;
            uint32_t B00 = *(const uint32_t*)(Bh + coff0 + kb);
            uint32_t B01 = *(const uint32_t*)(Bh + coff0 + kb + 16);
            uint32_t B10 = *(const uint32_t*)(Bh + coff1 + kb);
            uint32_t B11 = *(const uint32_t*)(Bh + coff1 + kb + 16);
            mma16816h(hh0, aHi[kc], B00, B01);
            mma16816h(lh0, aLo[kc], B00, B01);
            mma16816h(hh1, aHi[kc], B10, B11);
            mma16816h(lh1, aLo[kc], B10, B11);
        }
        {   // bias/emb lo correction (A-hi x B-lo, chunk 16)
            const uint32_t kb = (uint32_t)tg * 4;
            uint32_t L00 = *(const uint32_t*)(Bl + loff0 + kb);
            uint32_t L01 = *(const uint32_t*)(Bl + loff0 + kb + 16);
            uint32_t L10 = *(const uint32_t*)(Bl + loff1 + kb);
            uint32_t L11 = *(const uint32_t*)(Bl + loff1 + kb + 16);
            mma16816h(hh0, aHi[16], L00, L01);
            mma16816h(hh1, aHi[16], L10, L11);
        }
        // d-frag: c0=(row g, col 2tg) c1=(row g, 2tg+1) c2=(row g+8, 2tg) c3=(row g+8, 2tg+1)
        float d0n0 = hh0[0] + lh0[0];
        float d1n0 = hh0[1] + lh0[1];
        float d2n0 = hh0[2] + lh0[2];
        float d3n0 = hh0[3] + lh0[3];
        float d0n1 = hh1[0] + lh1[0];
        float d1n1 = hh1[1] + lh1[1];
        float d2n1 = hh1[2] + lh1[2];
        float d3n1 = hh1[3] + lh1[3];

        // ---- gate exchange with lane^16 (same j, other gate-pair) ----
        float sA0 = qa ? d0n0 : d1n0;
        float rA0 = __shfl_xor_sync(0xffffffffu, sA0, 16);
        float sB0 = qa ? d2n0 : d3n0;
        float rB0 = __shfl_xor_sync(0xffffffffu, sB0, 16);
        float pg00 = qa ? rA0 : d0n0;   // gate0 @ (j, cA)
        float pg10 = qa ? d1n0 : rA0;   // gate1
        float pg20 = qa ? rB0 : d2n0;   // gate2
        float pg30 = qa ? d3n0 : rB0;   // gate3

        float sA1 = qa ? d0n1 : d1n1;
        float rA1 = __shfl_xor_sync(0xffffffffu, sA1, 16);
        float sB1 = qa ? d2n1 : d3n1;
        float rB1 = __shfl_xor_sync(0xffffffffu, sB1, 16);
        float pg01 = qa ? rA1 : d0n1;
        float pg11 = qa ? d1n1 : rA1;
        float pg21 = qa ? rB1 : d2n1;
        float pg31 = qa ? d3n1 : rB1;

        // ---- activations + c/h update ----
        float g0 = tanhapx(pg00), i0 = sigapx(pg10), f0 = sigapx(pg20), o0 = sigapx(pg30);
        float g1 = tanhapx(pg01), i1 = sigapx(pg11), f1 = sigapx(pg21), o1 = sigapx(pg31);
        cst0 = fmaf(g0, i0, cst0 * f0);
        cst1 = fmaf(g1, i1, cst1 * f1);
        const float h0v = tanhapx(cst0) * o0;
        const float h1v = tanhapx(cst1) * o1;

        // ---- j-pair exchange with lane^4: (even j, odd j) same col ----
        float o0v = __shfl_xor_sync(0xffffffffu, h0v, 4);
        float o1v = __shfl_xor_sync(0xffffffffu, h1v, 4);
        float va = jlow ? h0v : o1v;    // k even
        float vb = jlow ? o0v : h1v;    // k odd
        const uint32_t pkt = pack_h2(va, vb);

        // ---- next-step embedding into own buffer p^1 (plain STS) ----
        if (tid < G_COLS && t + 1 < T_SEQ) {
            int xi = xbuf[(t + 1) * G_COLS + tid];
            uint32_t* Nh = (uint32_t*)(sb + OFF_BH + (p ^ 1) * BH_MAT) + tid * SHI_W;
            uint32_t* Nl = (uint32_t*)(sb + OFF_BL + (p ^ 1) * BL_MAT) + tid * 8;
            #pragma unroll
            for (int pe = 0; pe < 3; pe++) {
                Nh[130 + pe] = epk[xi * 6 + pe];
                Nl[2 + pe]   = epk[xi * 6 + 3 + pe];
            }
        }

        // ---- broadcast h k-pair (u32) to all 8 CTAs' buffer p^1 ----
        const uint32_t dOff = (uint32_t)(OFF_BH + (p ^ 1) * BH_MAT) + stCol;
        #pragma unroll
        for (int r = 0; r < CLUSTER; r++)
            st_cluster_u32(peer[r] + dOff, pkt);

        cluster_sync_();     // read-completion + write-visibility rendezvous
        p ^= 1;
    }

    // ---- projection: out[b, c] = sum_k Wp[c,k] h[k,b] + bp[c] (final h in buffer p) ----
    if (rank == 0 && tid < G_COLS * C_DIM) {
        const int col = tid / C_DIM;
        const int cls = tid % C_DIM;
        const uint32_t* Bc = (const uint32_t*)(sb + OFF_BH + p * BH_MAT) + col * SHI_W;
        const float* wpr = Wp + cls * H_DIM;
        float s = bp[cls];
        for (int kp = 0; kp < H_DIM / 2; kp++) {
            uint32_t w = Bc[kp];
            __half2 hv = *(__half2*)&w;
            s = fmaf(wpr[2 * kp],     __half2float(hv.x),
                fmaf(wpr[2 * kp + 1], __half2float(hv.y), s));
        }
        out[(col0 + col) * C_DIM + cls] = s;
    }
}

extern "C" void kernel_launch(void* const* d_in, const int* in_sizes, int n_in,
                              void* d_out, int out_size) {
    (void)in_sizes; (void)n_in; (void)out_size;
    const int*   x   = (const int*)  d_in[0];
    const float* emb = (const float*)d_in[1];
    const float* Wxg = (const float*)d_in[2];
    const float* Whg = (const float*)d_in[3];
    const float* bg  = (const float*)d_in[4];
    const float* Wxi = (const float*)d_in[5];
    const float* Whi = (const float*)d_in[6];
    const float* bi  = (const float*)d_in[7];
    const float* Wxf = (const float*)d_in[8];
    const float* Whf = (const float*)d_in[9];
    const float* bf  = (const float*)d_in[10];
    const float* Wxo = (const float*)d_in[11];
    const float* Who = (const float*)d_in[12];
    const float* bo  = (const float*)d_in[13];
    const float* Wp  = (const float*)d_in[14];
    const float* bp  = (const float*)d_in[15];
    float* out = (float*)d_out;

    cudaFuncSetAttribute(lstm_hmma_kernel,
                         cudaFuncAttributeMaxDynamicSharedMemorySize, SMEM_BYTES);
    lstm_hmma_kernel<<<(B_DIM / G_COLS) * CLUSTER, NTHREADS, SMEM_BYTES>>>(
        x, emb, Wxg, Whg, bg, Wxi, Whi, bi, Wxf, Whf, bf, Wxo, Who, bo, Wp, bp, out);
}

// round 11
// speedup vs baseline: 2.7460x; 1.2222x over previous
#include <cuda_runtime.h>
#include <cuda_fp16.h>
#include <cstdint>

#define T_SEQ   512
#define B_DIM   256
#define H_DIM   256
#define E_DIM   6
#define C_DIM   10
#define CLUSTER 8
#define G_COLS  16
#define NTHREADS 256
#define KC_N    16                  // 16 k-chunks of 16 -> K = 256 (h only)

// B: per column 132 words, fp16x2 per k-pair kp (0..127 = h, 128..131 pad)
//   stride 132 = 4 (mod 32) -> conflict-free LDS.32 across (g, tg)
#define SHI_W   132
#define B_MAT   (G_COLS * SHI_W * 4)             // 8448 B
#define OFF_BH   0                               // 2 ping-pong buffers
#define OFF_XB   (2 * B_MAT)                     // 16896 : x staged [t][col]
#define OFF_EMBF (OFF_XB + T_SEQ * G_COLS * 4)   // 49664 : emb fp32 [10][6]
#define SMEM_BYTES (OFF_EMBF + 240 + 16)

__device__ __forceinline__ uint32_t smem_u32(const void* p) {
    return (uint32_t)__cvta_generic_to_shared(p);
}
__device__ __forceinline__ uint32_t mapa_rank(uint32_t addr, int r) {
    uint32_t ret;
    asm("mapa.shared::cluster.u32 %0, %1, %2;" : "=r"(ret) : "r"(addr), "r"(r));
    return ret;
}
__device__ __forceinline__ void st_cluster_u32(uint32_t addr, uint32_t v) {
    asm volatile("st.shared::cluster.u32 [%0], %1;" :: "r"(addr), "r"(v) : "memory");
}
__device__ __forceinline__ void cluster_sync_() {
    asm volatile("barrier.cluster.arrive.aligned;\n\tbarrier.cluster.wait.aligned;" ::: "memory");
}
#define CL_ARRIVE() asm volatile("barrier.cluster.arrive.aligned;" ::: "memory")
#define CL_WAIT()   asm volatile("barrier.cluster.wait.aligned;" ::: "memory")

__device__ __forceinline__ void mma16816h(float c[4], const uint32_t a[4],
                                          uint32_t b0, uint32_t b1) {
    asm volatile("mma.sync.aligned.m16n8k16.row.col.f32.f16.f16.f32 "
                 "{%0,%1,%2,%3}, {%4,%5,%6,%7}, {%8,%9}, {%0,%1,%2,%3};"
                 : "+f"(c[0]), "+f"(c[1]), "+f"(c[2]), "+f"(c[3])
                 : "r"(a[0]), "r"(a[1]), "r"(a[2]), "r"(a[3]), "r"(b0), "r"(b1));
}
__device__ __forceinline__ uint32_t pack_h2(float a, float b) {
    __half2 t = __floats2half2_rn(a, b);
    return *(uint32_t*)&t;
}
__device__ __forceinline__ float tanhapx(float x) {
    float y;
    asm("tanh.approx.f32 %0, %1;" : "=f"(y) : "f"(x));
    return y;
}
__device__ __forceinline__ float sigapx(float x) {
    return fmaf(0.5f, tanhapx(0.5f * x), 0.5f);
}

extern "C" __global__ void __launch_bounds__(NTHREADS, 1) __cluster_dims__(CLUSTER, 1, 1)
lstm_hmma_kernel(const int* __restrict__ x, const float* __restrict__ emb,
                 const float* __restrict__ Wxg, const float* __restrict__ Whg, const float* __restrict__ bg,
                 const float* __restrict__ Wxi, const float* __restrict__ Whi, const float* __restrict__ bi,
                 const float* __restrict__ Wxf, const float* __restrict__ Whf, const float* __restrict__ bf,
                 const float* __restrict__ Wxo, const float* __restrict__ Who, const float* __restrict__ bo,
                 const float* __restrict__ Wp,  const float* __restrict__ bp,
                 float* __restrict__ out)
{
    extern __shared__ char sb[];
    int*   xbuf = (int*)(sb + OFF_XB);
    float* embf = (float*)(sb + OFF_EMBF);
    const uint32_t sb32 = smem_u32(sb);

    const int tid  = threadIdx.x;
    const int wid  = tid >> 5;
    const int lane = tid & 31;
    const int g    = lane >> 2;       // groupID 0..7
    const int tg   = lane & 3;        // thread-in-group
    const int qa   = g >> 2;          // gate-pair selector
    const int rank = blockIdx.x & (CLUSTER - 1);
    const int cid  = blockIdx.x / CLUSTER;
    const int col0 = cid * G_COLS;

    const float* WhTab[4] = { Whg, Whi, Whf, Who };
    const float* WxTab[4] = { Wxg, Wxi, Wxf, Wxo };
    const float* bTab[4]  = { bg,  bi,  bf,  bo  };

    // ---- A fragments: Wh only, single fp16 pass, remapped rows ----
    // warp tile row r (0..15): gate = r>>2, j = 4*wid + (r&3)
    uint32_t aHi[KC_N][4];
    {
        auto getA = [&](int r, int k) -> float {
            int gate = r >> 2, j = 4 * wid + (r & 3);
            return WhTab[gate][(rank * 32 + j) * H_DIM + k];
        };
        const int ra = g, rb = g + 8;
        #pragma unroll
        for (int kc = 0; kc < KC_N; kc++) {
            const int k0 = kc * 16 + 2 * tg;
            aHi[kc][0] = pack_h2(getA(ra, k0),     getA(ra, k0 + 1));
            aHi[kc][1] = pack_h2(getA(rb, k0),     getA(rb, k0 + 1));
            aHi[kc][2] = pack_h2(getA(ra, k0 + 8), getA(ra, k0 + 9));
            aHi[kc][3] = pack_h2(getA(rb, k0 + 8), getA(rb, k0 + 9));
        }
    }

    // thread-owned output mapping (j = 4*wid + (g&3))
    const int jloc = 4 * wid + (g & 3);
    const int cA   = 2 * tg + qa;
    const int cB   = cA + 8;
    const int jlow = ((g & 1) == 0);
    const int kpl  = 2 * wid + ((g & 3) >> 1);
    const uint32_t stCol = (uint32_t)(((jlow ? cA : cB) * SHI_W + rank * 16 + kpl) * 4);

    // ---- epilogue constants in registers: Wx row + bias per owned column ----
    float wxr[4][E_DIM], biasA[4], biasB[4];
    #pragma unroll
    for (int q = 0; q < 4; q++) {
        const float* wx = WxTab[q] + (rank * 32 + jloc) * E_DIM;
        #pragma unroll
        for (int e = 0; e < E_DIM; e++) wxr[q][e] = wx[e];
        biasA[q] = bTab[q][col0 + cA];
        biasB[q] = bTab[q][col0 + cB];
    }

    // ---- zero both B buffers (h0 = 0, pads) ----
    for (int i = tid; i < (2 * B_MAT) / 4; i += NTHREADS)
        ((uint32_t*)(sb + OFF_BH))[i] = 0u;
    // ---- stage x sequence + fp32 emb table ----
    for (int i = tid; i < G_COLS * T_SEQ; i += NTHREADS) {
        int c = i >> 9, t = i & 511;
        xbuf[t * G_COLS + c] = x[(col0 + c) * T_SEQ + t];
    }
    if (tid < 10 * E_DIM) embf[tid] = emb[tid];

    uint32_t peer[CLUSTER];
    #pragma unroll
    for (int r = 0; r < CLUSTER; r++) peer[r] = mapa_rank(sb32, r);

    __syncthreads();
    cluster_sync_();
    CL_ARRIVE();                 // pairs with the wait at t=0

    const uint32_t coff0 = (uint32_t)(g * SHI_W * 4);
    const uint32_t coff1 = (uint32_t)((8 + g) * SHI_W * 4);
    float cst0 = 0.0f, cst1 = 0.0f;

    int p = 0;
    for (int t = 0; t < T_SEQ; t++) {
        // ---- preX: bias + Wx*x_t (independent of h; overlaps barrier skew) ----
        int xiA = xbuf[t * G_COLS + cA];
        int xiB = xbuf[t * G_COLS + cB];
        const float* eA = embf + xiA * E_DIM;
        const float* eB = embf + xiB * E_DIM;
        float pXA[4], pXB[4];
        #pragma unroll
        for (int q = 0; q < 4; q++) { pXA[q] = biasA[q]; pXB[q] = biasB[q]; }
        #pragma unroll
        for (int e = 0; e < E_DIM; e++) {
            float ea = eA[e], eb = eB[e];
            #pragma unroll
            for (int q = 0; q < 4; q++) {
                pXA[q] = fmaf(wxr[q][e], ea, pXA[q]);
                pXB[q] = fmaf(wxr[q][e], eb, pXB[q]);
            }
        }

        CL_WAIT();               // peers' stores for this step visible; reads of p^1 done

        // ---- MMA: single fp16 pass, 16 chunks x 2 n-tiles ----
        const char* Bp = sb + OFF_BH + p * B_MAT;
        float hh0[4] = {0,0,0,0};
        float hh1[4] = {0,0,0,0};
        #pragma unroll
        for (int kc = 0; kc < KC_N; kc++) {
            const uint32_t kb = (uint32_t)(8 * kc + tg) * 4;
            uint32_t B00 = *(const uint32_t*)(Bp + coff0 + kb);
            uint32_t B01 = *(const uint32_t*)(Bp + coff0 + kb + 16);
            uint32_t B10 = *(const uint32_t*)(Bp + coff1 + kb);
            uint32_t B11 = *(const uint32_t*)(Bp + coff1 + kb + 16);
            mma16816h(hh0, aHi[kc], B00, B01);
            mma16816h(hh1, aHi[kc], B10, B11);
        }
        // d-frag: c0=(row g, col 2tg) c1=(row g, 2tg+1) c2=(row g+8, 2tg) c3=(row g+8, 2tg+1)
        // row g -> gate qa; row g+8 -> gate qa+2; same j.

        // ---- gate exchange with lane^16 (same j, other gate-pair) ----
        float sA0 = qa ? hh0[0] : hh0[1];
        float rA0 = __shfl_xor_sync(0xffffffffu, sA0, 16);
        float sB0 = qa ? hh0[2] : hh0[3];
        float rB0 = __shfl_xor_sync(0xffffffffu, sB0, 16);
        float pg00 = (qa ? rA0 : hh0[0]) + pXA[0];   // gate0 @ (j, cA)
        float pg10 = (qa ? hh0[1] : rA0) + pXA[1];   // gate1
        float pg20 = (qa ? rB0 : hh0[2]) + pXA[2];   // gate2
        float pg30 = (qa ? hh0[3] : rB0) + pXA[3];   // gate3

        float sA1 = qa ? hh1[0] : hh1[1];
        float rA1 = __shfl_xor_sync(0xffffffffu, sA1, 16);
        float sB1 = qa ? hh1[2] : hh1[3];
        float rB1 = __shfl_xor_sync(0xffffffffu, sB1, 16);
        float pg01 = (qa ? rA1 : hh1[0]) + pXB[0];
        float pg11 = (qa ? hh1[1] : rA1) + pXB[1];
        float pg21 = (qa ? rB1 : hh1[2]) + pXB[2];
        float pg31 = (qa ? hh1[3] : rB1) + pXB[3];

        // ---- activations + c/h update ----
        float g0 = tanhapx(pg00), i0 = sigapx(pg10), f0 = sigapx(pg20), o0 = sigapx(pg30);
        float g1 = tanhapx(pg01), i1 = sigapx(pg11), f1 = sigapx(pg21), o1 = sigapx(pg31);
        cst0 = fmaf(g0, i0, cst0 * f0);
        cst1 = fmaf(g1, i1, cst1 * f1);
        const float h0v = tanhapx(cst0) * o0;
        const float h1v = tanhapx(cst1) * o1;

        // ---- j-pair exchange with lane^4: (even j, odd j) same col ----
        float o0v = __shfl_xor_sync(0xffffffffu, h0v, 4);
        float o1v = __shfl_xor_sync(0xffffffffu, h1v, 4);
        float va = jlow ? h0v : o1v;    // k even
        float vb = jlow ? o0v : h1v;    // k odd
        const uint32_t pkt = pack_h2(va, vb);

        // ---- broadcast h k-pair (u32) to all 8 CTAs' buffer p^1 ----
        const uint32_t dOff = (uint32_t)(OFF_BH + (p ^ 1) * B_MAT) + stCol;
        #pragma unroll
        for (int r = 0; r < CLUSTER; r++)
            st_cluster_u32(peer[r] + dOff, pkt);

        CL_ARRIVE();             // release stores; consumed by peers' wait at t+1
        p ^= 1;
    }

    CL_WAIT();                   // final arrives: t=511 stores (into B[0]) visible

    // ---- projection: out[b, c] = sum_k Wp[c,k] h[k,b] + bp[c] (final h in B[0]) ----
    if (rank == 0 && tid < G_COLS * C_DIM) {
        const int col = tid / C_DIM;
        const int cls = tid % C_DIM;
        const uint32_t* Bc = (const uint32_t*)(sb + OFF_BH) + col * SHI_W;
        const float* wpr = Wp + cls * H_DIM;
        float s = bp[cls];
        for (int kp = 0; kp < H_DIM / 2; kp++) {
            uint32_t w = Bc[kp];
            __half2 hv = *(__half2*)&w;
            s = fmaf(wpr[2 * kp],     __half2float(hv.x),
                fmaf(wpr[2 * kp + 1], __half2float(hv.y), s));
        }
        out[(col0 + col) * C_DIM + cls] = s;
    }
}

extern "C" void kernel_launch(void* const* d_in, const int* in_sizes, int n_in,
                              void* d_out, int out_size) {
    (void)in_sizes; (void)n_in; (void)out_size;
    const int*   x   = (const int*)  d_in[0];
    const float* emb = (const float*)d_in[1];
    const float* Wxg = (const float*)d_in[2];
    const float* Whg = (const float*)d_in[3];
    const float* bg  = (const float*)d_in[4];
    const float* Wxi = (const float*)d_in[5];
    const float* Whi = (const float*)d_in[6];
    const float* bi  = (const float*)d_in[7];
    const float* Wxf = (const float*)d_in[8];
    const float* Whf = (const float*)d_in[9];
    const float* bf  = (const float*)d_in[10];
    const float* Wxo = (const float*)d_in[11];
    const float* Who = (const float*)d_in[12];
    const float* bo  = (const float*)d_in[13];
    const float* Wp  = (const float*)d_in[14];
    const float* bp  = (const float*)d_in[15];
    float* out = (float*)d_out;

    cudaFuncSetAttribute(lstm_hmma_kernel,
                         cudaFuncAttributeMaxDynamicSharedMemorySize, SMEM_BYTES);
    lstm_hmma_kernel<<<(B_DIM / G_COLS) * CLUSTER, NTHREADS, SMEM_BYTES>>>(
        x, emb, Wxg, Whg, bg, Wxi, Whi, bi, Wxf, Whf, bf, Wxo, Who, bo, Wp, bp, out);
}

// round 13
// speedup vs baseline: 7.0694x; 2.5744x over previous
#include <cuda_runtime.h>
#include <cuda_fp16.h>
#include <cstdint>

#define T_SEQ   512
#define B_DIM   256
#define H_DIM   256
#define E_DIM   6
#define C_DIM   10
#define CLUSTER 4
#define G_COLS  8
#define NTHREADS 512
#define KC_N    16                  // 16 k-chunks of 16 -> K = 256 (h only)

// B: per column 132 words, fp16x2 per k-pair kp (0..127 = h, 128..131 pad)
//   stride 132 = 4 (mod 32) -> conflict-free LDS.32 across (g, tg)
#define SHI_W   132
#define B_MAT   (G_COLS * SHI_W * 4)             // 4224 B
#define OFF_BH   0                               // 2 ping-pong buffers (8448)
#define OFF_XB   (2 * B_MAT)                     // 8448 : x staged [t][col] (16384)
#define OFF_EMBF (OFF_XB + T_SEQ * G_COLS * 4)   // 24832 : emb fp32 [10][6] (240)
#define OFF_WXS  (OFF_EMBF + 240)                // 25072 : Wx fp32 [64][4][6] (6144)
#define OFF_BSH  (OFF_WXS + 6144)                // 31216 : bias fp32 [4][8] (128)
#define SMEM_BYTES (OFF_BSH + 128 + 16)

__device__ __forceinline__ uint32_t smem_u32(const void* p) {
    return (uint32_t)__cvta_generic_to_shared(p);
}
__device__ __forceinline__ uint32_t mapa_rank(uint32_t addr, int r) {
    uint32_t ret;
    asm("mapa.shared::cluster.u32 %0, %1, %2;" : "=r"(ret) : "r"(addr), "r"(r));
    return ret;
}
__device__ __forceinline__ void st_cluster_u32(uint32_t addr, uint32_t v) {
    asm volatile("st.shared::cluster.u32 [%0], %1;" :: "r"(addr), "r"(v) : "memory");
}
__device__ __forceinline__ void cluster_sync_() {
    asm volatile("barrier.cluster.arrive.aligned;\n\tbarrier.cluster.wait.aligned;" ::: "memory");
}
#define CL_ARRIVE() asm volatile("barrier.cluster.arrive.aligned;" ::: "memory")
#define CL_WAIT()   asm volatile("barrier.cluster.wait.aligned;" ::: "memory")

__device__ __forceinline__ void mma16816h(float c[4], const uint32_t a[4],
                                          uint32_t b0, uint32_t b1) {
    asm volatile("mma.sync.aligned.m16n8k16.row.col.f32.f16.f16.f32 "
                 "{%0,%1,%2,%3}, {%4,%5,%6,%7}, {%8,%9}, {%0,%1,%2,%3};"
                 : "+f"(c[0]), "+f"(c[1]), "+f"(c[2]), "+f"(c[3])
                 : "r"(a[0]), "r"(a[1]), "r"(a[2]), "r"(a[3]), "r"(b0), "r"(b1));
}
__device__ __forceinline__ uint32_t pack_h2(float a, float b) {
    __half2 t = __floats2half2_rn(a, b);
    return *(uint32_t*)&t;
}
__device__ __forceinline__ float tanhapx(float x) {
    float y;
    asm("tanh.approx.f32 %0, %1;" : "=f"(y) : "f"(x));
    return y;
}
__device__ __forceinline__ float sigapx(float x) {
    return fmaf(0.5f, tanhapx(0.5f * x), 0.5f);
}

extern "C" __global__ void __launch_bounds__(NTHREADS, 1) __cluster_dims__(CLUSTER, 1, 1)
lstm_hmma_kernel(const int* __restrict__ x, const float* __restrict__ emb,
                 const float* __restrict__ Wxg, const float* __restrict__ Whg, const float* __restrict__ bg,
                 const float* __restrict__ Wxi, const float* __restrict__ Whi, const float* __restrict__ bi,
                 const float* __restrict__ Wxf, const float* __restrict__ Whf, const float* __restrict__ bf,
                 const float* __restrict__ Wxo, const float* __restrict__ Who, const float* __restrict__ bo,
                 const float* __restrict__ Wp,  const float* __restrict__ bp,
                 float* __restrict__ out)
{
    extern __shared__ char sb[];
    int*   xbuf = (int*)(sb + OFF_XB);
    float* embf = (float*)(sb + OFF_EMBF);
    float* wxs  = (float*)(sb + OFF_WXS);     // [j][gate][e]
    float* bsh  = (float*)(sb + OFF_BSH);     // [gate][col]
    const uint32_t sb32 = smem_u32(sb);

    const int tid  = threadIdx.x;
    const int wid  = tid >> 5;        // 0..15, one m16n8 tile per warp
    const int lane = tid & 31;
    const int g    = lane >> 2;       // groupID 0..7
    const int tg   = lane & 3;        // thread-in-group
    const int qa   = g >> 2;          // gate-pair selector
    const int rank = blockIdx.x & (CLUSTER - 1);
    const int cid  = blockIdx.x / CLUSTER;
    const int col0 = cid * G_COLS;

    const float* WhTab[4] = { Whg, Whi, Whf, Who };
    const float* WxTab[4] = { Wxg, Wxi, Wxf, Wxo };
    const float* bTab[4]  = { bg,  bi,  bf,  bo  };

    // ---- A fragments: Wh fp16, remapped rows ----
    // warp tile row r (0..15): gate = r>>2, j = 4*wid + (r&3)  (j = 0..63)
    uint32_t aHi[KC_N][4];
    {
        auto getA = [&](int r, int k) -> float {
            int gate = r >> 2, j = 4 * wid + (r & 3);
            return WhTab[gate][(rank * 64 + j) * H_DIM + k];
        };
        const int ra = g, rb = g + 8;
        #pragma unroll
        for (int kc = 0; kc < KC_N; kc++) {
            const int k0 = kc * 16 + 2 * tg;
            aHi[kc][0] = pack_h2(getA(ra, k0),     getA(ra, k0 + 1));
            aHi[kc][1] = pack_h2(getA(rb, k0),     getA(rb, k0 + 1));
            aHi[kc][2] = pack_h2(getA(ra, k0 + 8), getA(ra, k0 + 9));
            aHi[kc][3] = pack_h2(getA(rb, k0 + 8), getA(rb, k0 + 9));
        }
    }

    // thread-owned output mapping
    const int jloc = 4 * wid + (g & 3);          // 0..63
    const int cA   = 2 * tg + qa;                // owned column 0..7
    const int jlow = ((g & 1) == 0);
    const int kpl  = 2 * wid + ((g & 3) >> 1);   // j>>1, 0..31
    const uint32_t stCol = (uint32_t)((cA * SHI_W + rank * 32 + kpl) * 4);

    // ---- smem init: B zero, x staged, emb, Wx, bias ----
    for (int i = tid; i < (2 * B_MAT) / 4; i += NTHREADS)
        ((uint32_t*)(sb + OFF_BH))[i] = 0u;
    for (int i = tid; i < G_COLS * T_SEQ; i += NTHREADS) {
        int c = i >> 9, t = i & 511;
        xbuf[t * G_COLS + c] = x[(col0 + c) * T_SEQ + t];
    }
    if (tid < 10 * E_DIM) embf[tid] = emb[tid];
    for (int i = tid; i < 64 * 4 * E_DIM; i += NTHREADS) {
        int j = i / (4 * E_DIM), rr = i % (4 * E_DIM);
        int q = rr / E_DIM, e = rr % E_DIM;
        wxs[i] = WxTab[q][(rank * 64 + j) * E_DIM + e];
    }
    if (tid < 32) {
        int q = tid >> 3, c = tid & 7;
        bsh[tid] = bTab[q][col0 + c];
    }

    uint32_t peerA, peerB;   // this thread's two store targets
    {
        uint32_t pr[CLUSTER];
        #pragma unroll
        for (int r = 0; r < CLUSTER; r++) pr[r] = mapa_rank(sb32, r);
        peerA = jlow ? pr[0] : pr[2];
        peerB = jlow ? pr[1] : pr[3];
    }

    __syncthreads();
    cluster_sync_();
    CL_ARRIVE();                 // pairs with the wait at t=0

    const uint32_t coff = (uint32_t)(g * SHI_W * 4);
    float cst = 0.0f;

    int p = 0;
    for (int t = 0; t < T_SEQ; t++) {
        // ---- preX: bias + Wx*x_t for (jloc, cA) — overlaps barrier skew ----
        int xi = xbuf[t * G_COLS + cA];
        const float* ev = embf + xi * E_DIM;
        const float* wxr = wxs + jloc * (4 * E_DIM);
        float pX[4];
        #pragma unroll
        for (int q = 0; q < 4; q++) pX[q] = bsh[q * 8 + cA];
        #pragma unroll
        for (int e = 0; e < E_DIM; e++) {
            float ee = ev[e];
            #pragma unroll
            for (int q = 0; q < 4; q++)
                pX[q] = fmaf(wxr[q * E_DIM + e], ee, pX[q]);
        }

        CL_WAIT();               // peers' stores visible; buffer p^1 reads done

        // ---- MMA: 16 chunks, 2 independent chains of 8 ----
        const char* Bp = sb + OFF_BH + p * B_MAT;
        float h0[4] = {0,0,0,0}, h1[4] = {0,0,0,0};
        #pragma unroll
        for (int kc = 0; kc < 8; kc++) {
            const uint32_t kbA = (uint32_t)(8 * kc + tg) * 4;
            const uint32_t kbB = (uint32_t)(8 * (kc + 8) + tg) * 4;
            uint32_t A0 = *(const uint32_t*)(Bp + coff + kbA);
            uint32_t A1 = *(const uint32_t*)(Bp + coff + kbA + 16);
            uint32_t B0 = *(const uint32_t*)(Bp + coff + kbB);
            uint32_t B1 = *(const uint32_t*)(Bp + coff + kbB + 16);
            mma16816h(h0, aHi[kc],     A0, A1);
            mma16816h(h1, aHi[kc + 8], B0, B1);
        }
        float d0 = h0[0] + h1[0];    // (gate qa,   col 2tg)
        float d1 = h0[1] + h1[1];    // (gate qa,   col 2tg+1)
        float d2 = h0[2] + h1[2];    // (gate qa+2, col 2tg)
        float d3 = h0[3] + h1[3];    // (gate qa+2, col 2tg+1)

        // ---- gate exchange with lane^16 (same j, other gate-pair) ----
        float sA = qa ? d0 : d1;
        float rA = __shfl_xor_sync(0xffffffffu, sA, 16);
        float sB = qa ? d2 : d3;
        float rB = __shfl_xor_sync(0xffffffffu, sB, 16);
        float pg0 = (qa ? rA : d0) + pX[0];   // gate g
        float pg1 = (qa ? d1 : rA) + pX[1];   // gate i
        float pg2 = (qa ? rB : d2) + pX[2];   // gate f
        float pg3 = (qa ? d3 : rB) + pX[3];   // gate o

        // ---- activations + c/h update for (jloc, cA) ----
        float gg = tanhapx(pg0), ii = sigapx(pg1), ff = sigapx(pg2), oo = sigapx(pg3);
        cst = fmaf(gg, ii, cst * ff);
        const float hv = tanhapx(cst) * oo;

        // ---- j-pair exchange with lane^4: (even j, odd j) same col ----
        float ov = __shfl_xor_sync(0xffffffffu, hv, 4);
        float va = jlow ? hv : ov;    // k even
        float vb = jlow ? ov : hv;    // k odd
        const uint32_t pkt = pack_h2(va, vb);

        // ---- store pkt to 2 of 4 peers (partner covers the other 2) ----
        const uint32_t dOff = (uint32_t)(OFF_BH + (p ^ 1) * B_MAT) + stCol;
        st_cluster_u32(peerA + dOff, pkt);
        st_cluster_u32(peerB + dOff, pkt);

        CL_ARRIVE();             // release stores; consumed by peers' wait at t+1
        p ^= 1;
    }

    CL_WAIT();                   // t=511 stores (into B[0]) visible

    // ---- projection: out[b, c] = sum_k Wp[c,k] h[k,b] + bp[c] (final h in B[0]) ----
    if (rank == 0 && tid < G_COLS * C_DIM) {
        const int col = tid / C_DIM;
        const int cls = tid % C_DIM;
        const uint32_t* Bc = (const uint32_t*)(sb + OFF_BH) + col * SHI_W;
        const float* wpr = Wp + cls * H_DIM;
        float s = bp[cls];
        for (int kp = 0; kp < H_DIM / 2; kp++) {
            uint32_t w = Bc[kp];
            __half2 hw = *(__half2*)&w;
            s = fmaf(wpr[2 * kp],     __half2float(hw.x),
                fmaf(wpr[2 * kp + 1], __half2float(hw.y), s));
        }
        out[(col0 + col) * C_DIM + cls] = s;
    }
}

extern "C" void kernel_launch(void* const* d_in, const int* in_sizes, int n_in,
                              void* d_out, int out_size) {
    (void)in_sizes; (void)n_in; (void)out_size;
    const int*   x   = (const int*)  d_in[0];
    const float* emb = (const float*)d_in[1];
    const float* Wxg = (const float*)d_in[2];
    const float* Whg = (const float*)d_in[3];
    const float* bg  = (const float*)d_in[4];
    const float* Wxi = (const float*)d_in[5];
    const float* Whi = (const float*)d_in[6];
    const float* bi  = (const float*)d_in[7];
    const float* Wxf = (const float*)d_in[8];
    const float* Whf = (const float*)d_in[9];
    const float* bf  = (const float*)d_in[10];
    const float* Wxo = (const float*)d_in[11];
    const float* Who = (const float*)d_in[12];
    const float* bo  = (const float*)d_in[13];
    const float* Wp  = (const float*)d_in[14];
    const float* bp  = (const float*)d_in[15];
    float* out = (float*)d_out;

    cudaFuncSetAttribute(lstm_hmma_kernel,
                         cudaFuncAttributeMaxDynamicSharedMemorySize, SMEM_BYTES);
    // 32 clusters of 4 CTAs = 128 CTAs
    lstm_hmma_kernel<<<(B_DIM / G_COLS) * CLUSTER, NTHREADS, SMEM_BYTES>>>(
        x, emb, Wxg, Whg, bg, Wxi, Whi, bi, Wxf, Whf, bf, Wxo, Who, bo, Wp, bp, out);
}